// round 3
// baseline (speedup 1.0000x reference)
#include <cuda_runtime.h>

#define Nn   100000
#define Ee   3200000
#define FIN  128
#define H1   32
#define H2   64
#define NG   256
#define ACT  64

// ---------------- scratch (device globals; no allocation allowed) ----------
__device__ float    g_deg [Nn];        // degree, then overwritten with dinv
__device__ float    g_h1  [Nn * H1];   // x @ W1
__device__ float    g_agg1[Nn * H1];   // GCN1 aggregate
__device__ float    g_h2  [Nn * H2];   // leaky(agg1+b1) @ W2
__device__ float    g_agg2[Nn * H2];   // GCN2 aggregate
__device__ unsigned g_pool[NG * H2];   // encoded segment max

// ---------------- helpers --------------------------------------------------
__device__ __forceinline__ float leaky(float v) { return v > 0.f ? v : 0.1f * v; }

// monotonic float->uint encoding for atomicMax-based segment max
__device__ __forceinline__ unsigned enc_f(float f) {
    unsigned u = __float_as_uint(f);
    return (u & 0x80000000u) ? ~u : (u | 0x80000000u);
}
__device__ __forceinline__ float dec_f(unsigned u) {
    return __uint_as_float((u & 0x80000000u) ? (u & 0x7fffffffu) : ~u);
}

// ---------------- kernels --------------------------------------------------
__global__ void k_init() {
    int i = blockIdx.x * blockDim.x + threadIdx.x;
    if (i < Nn)      g_deg[i]  = 1.0f;     // self-loop contributes 1
    if (i < NG * H2) g_pool[i] = 0u;       // below enc of any finite float
}

__global__ void k_deg(const int* __restrict__ dst, int E) {
    int e = blockIdx.x * blockDim.x + threadIdx.x;
    if (e < E) atomicAdd(&g_deg[dst[e]], 1.0f);
}

__global__ void k_dinv() {
    int i = blockIdx.x * blockDim.x + threadIdx.x;
    if (i < Nn) g_deg[i] = rsqrtf(g_deg[i]);   // deg >= 1 always
}

// h1 = x @ W1 ; agg1 = h1 * dinv^2 (self-loop term, also serves as init)
__global__ void k_gemm1(const float* __restrict__ x, const float* __restrict__ W1) {
    __shared__ float ws[FIN * H1];   // 16 KB
    __shared__ float xs[8][FIN];     // 4 KB
    for (int i = threadIdx.x; i < FIN * H1; i += 256) ws[i] = W1[i];
    const int c  = threadIdx.x & 31;
    const int ry = threadIdx.x >> 5;
    const int ngrp = (Nn + 7) / 8;
    for (int rg = blockIdx.x; rg < ngrp; rg += gridDim.x) {
        __syncthreads();
        const int base = rg * 8;
        for (int i = threadIdx.x; i < 8 * FIN; i += 256) {
            int r = i >> 7, k = i & 127;
            int row = base + r;
            xs[r][k] = (row < Nn) ? x[row * FIN + k] : 0.f;
        }
        __syncthreads();
        const int row = base + ry;
        if (row < Nn) {
            float acc = 0.f;
            #pragma unroll 8
            for (int k = 0; k < FIN; k++) acc += xs[ry][k] * ws[k * H1 + c];
            float di = g_deg[row];               // dinv
            g_h1  [row * H1 + c] = acc;
            g_agg1[row * H1 + c] = acc * di * di;
        }
    }
}

// layer-1 edge scatter: 8 threads per edge, float4 vector reductions
__global__ void k_scatter1(const int* __restrict__ src, const int* __restrict__ dst, int E) {
    long long tid = (long long)blockIdx.x * blockDim.x + threadIdx.x;
    if (tid >= (long long)E * 8) return;
    int e = (int)(tid >> 3), c = (int)(tid & 7);
    int s = src[e], d = dst[e];
    float w = g_deg[s] * g_deg[d];
    float4 v = *(const float4*)(g_h1 + (size_t)s * H1 + c * 4);
    float* p = g_agg1 + (size_t)d * H1 + c * 4;
    asm volatile("red.global.add.v4.f32 [%0], {%1,%2,%3,%4};"
                 :: "l"(p), "f"(v.x * w), "f"(v.y * w), "f"(v.z * w), "f"(v.w * w)
                 : "memory");
}

// h2 = leaky(agg1 + b1) @ W2 ; agg2 = h2 * dinv^2
__global__ void k_gemm2(const float* __restrict__ W2, const float* __restrict__ b1) {
    __shared__ float ws[H1 * H2];   // 8 KB
    __shared__ float bs[H1];
    __shared__ float xs[4][H1];
    for (int i = threadIdx.x; i < H1 * H2; i += 256) ws[i] = W2[i];
    if (threadIdx.x < H1) bs[threadIdx.x] = b1[threadIdx.x];
    const int c  = threadIdx.x & 63;
    const int ry = threadIdx.x >> 6;
    const int ngrp = (Nn + 3) / 4;
    for (int rg = blockIdx.x; rg < ngrp; rg += gridDim.x) {
        __syncthreads();
        const int base = rg * 4;
        for (int i = threadIdx.x; i < 4 * H1; i += 256) {
            int r = i >> 5, k = i & 31;
            int row = base + r;
            float v = (row < Nn) ? g_agg1[(size_t)row * H1 + k] + bs[k] : 0.f;
            xs[r][k] = leaky(v);
        }
        __syncthreads();
        const int row = base + ry;
        if (row < Nn) {
            float acc = 0.f;
            #pragma unroll
            for (int k = 0; k < H1; k++) acc += xs[ry][k] * ws[k * H2 + c];
            float di = g_deg[row];
            g_h2  [(size_t)row * H2 + c] = acc;
            g_agg2[(size_t)row * H2 + c] = acc * di * di;
        }
    }
}

// layer-2 edge scatter: 16 threads per edge, float4 vector reductions
__global__ void k_scatter2(const int* __restrict__ src, const int* __restrict__ dst, int E) {
    long long tid = (long long)blockIdx.x * blockDim.x + threadIdx.x;
    if (tid >= (long long)E * 16) return;
    int e = (int)(tid >> 4), c = (int)(tid & 15);
    int s = src[e], d = dst[e];
    float w = g_deg[s] * g_deg[d];
    float4 v = *(const float4*)(g_h2 + (size_t)s * H2 + c * 4);
    float* p = g_agg2 + (size_t)d * H2 + c * 4;
    asm volatile("red.global.add.v4.f32 [%0], {%1,%2,%3,%4};"
                 :: "l"(p), "f"(v.x * w), "f"(v.y * w), "f"(v.z * w), "f"(v.w * w)
                 : "memory");
}

// global max pool over batch segments (encoded atomicMax)
__global__ void k_pool(const int* __restrict__ batch, const float* __restrict__ b2) {
    int tid = blockIdx.x * blockDim.x + threadIdx.x;
    if (tid >= Nn * H2) return;
    int node = tid >> 6, f = tid & 63;
    float v = g_agg2[tid] + b2[f];
    atomicMax(&g_pool[batch[node] * H2 + f], enc_f(v));
}

// 3-layer MLP head: one block per graph
__global__ void k_mlp(const float* __restrict__ l1W, const float* __restrict__ l1b,
                      const float* __restrict__ l2W, const float* __restrict__ l2b,
                      const float* __restrict__ l3W, const float* __restrict__ l3b,
                      float* __restrict__ out) {
    __shared__ float gv[H2], z1[128], z2[64];
    const int g = blockIdx.x, t = threadIdx.x;
    if (t < H2) gv[t] = dec_f(g_pool[g * H2 + t]);
    __syncthreads();
    {   // [64] @ [64,128]
        float acc = l1b[t];
        #pragma unroll 8
        for (int k = 0; k < 64; k++) acc += gv[k] * l1W[k * 128 + t];
        z1[t] = leaky(acc);
    }
    __syncthreads();
    if (t < 64) {   // [128] @ [128,64]
        float acc = l2b[t];
        #pragma unroll 8
        for (int k = 0; k < 128; k++) acc += z1[k] * l2W[k * 64 + t];
        z2[t] = leaky(acc);
    }
    __syncthreads();
    if (t < 64) {   // [64] @ [64,64]
        float acc = l3b[t];
        #pragma unroll 8
        for (int k = 0; k < 64; k++) acc += z2[k] * l3W[k * 64 + t];
        out[g * 64 + t] = acc;
    }
}

// ---------------- launch ---------------------------------------------------
extern "C" void kernel_launch(void* const* d_in, const int* in_sizes, int n_in,
                              void* d_out, int out_size) {
    const float* x    = (const float*)d_in[0];
    const int*   ei   = (const int*)  d_in[1];   // [2,E]: src then dst
    const int*   batch= (const int*)  d_in[2];
    const float* W1   = (const float*)d_in[3];
    const float* b1   = (const float*)d_in[4];
    const float* W2   = (const float*)d_in[5];
    const float* b2   = (const float*)d_in[6];
    const float* l1W  = (const float*)d_in[7];
    const float* l1b  = (const float*)d_in[8];
    const float* l2W  = (const float*)d_in[9];
    const float* l2b  = (const float*)d_in[10];
    const float* l3W  = (const float*)d_in[11];
    const float* l3b  = (const float*)d_in[12];
    float* out = (float*)d_out;

    const int E = in_sizes[1] / 2;               // robust to shape variant
    const int* src = ei;
    const int* dst = ei + E;

    k_init <<<(Nn + 255) / 256, 256>>>();
    k_deg  <<<(E + 255) / 256, 256>>>(dst, E);
    k_dinv <<<(Nn + 255) / 256, 256>>>();
    k_gemm1<<<1480, 256>>>(x, W1);
    k_scatter1<<<(int)(((long long)E * 8 + 255) / 256), 256>>>(src, dst, E);
    k_gemm2<<<1480, 256>>>(W2, b1);
    k_scatter2<<<(int)(((long long)E * 16 + 255) / 256), 256>>>(src, dst, E);
    k_pool <<<(Nn * H2 + 255) / 256, 256>>>(batch, b2);
    k_mlp  <<<NG, 128>>>(l1W, l1b, l2W, l2b, l3W, l3b, out);
}

// round 4
// speedup vs baseline: 1.4839x; 1.4839x over previous
#include <cuda_runtime.h>

#define Nn   100000
#define Ee   3200000
#define FIN  128
#define H1   32
#define H2   64
#define NG   256

#define SB   256
#define NSB  ((Nn + SB - 1) / SB)   // 391

// ---------------- scratch ---------------------------------------------------
__device__ int      g_cnt[Nn];
__device__ int      g_row[Nn + 1];
__device__ int      g_cur[Nn];
__device__ int      g_srt[Ee];         // edge srcs sorted by dst
__device__ int      g_part[NSB];
__device__ float    g_dinv[Nn];
__device__ float    g_h1 [Nn * H1];    // (x@W1) * dinv
__device__ float    g_a1 [Nn * H1];    // GCN1 aggregate (pre-bias)
__device__ float    g_h2 [Nn * H2];    // (leaky(a1+b1)@W2) * dinv
__device__ unsigned g_pool[NG * H2];   // encoded segment max

// ---------------- helpers ---------------------------------------------------
__device__ __forceinline__ float leaky(float v) { return v > 0.f ? v : 0.1f * v; }
__device__ __forceinline__ unsigned enc_f(float f) {
    unsigned u = __float_as_uint(f);
    return (u & 0x80000000u) ? ~u : (u | 0x80000000u);
}
__device__ __forceinline__ float dec_f(unsigned u) {
    return __uint_as_float((u & 0x80000000u) ? (u & 0x7fffffffu) : ~u);
}

// ---------------- CSR build --------------------------------------------------
__global__ void k_init() {
    int i = blockIdx.x * blockDim.x + threadIdx.x;
    if (i < Nn)      g_cnt[i]  = 0;
    if (i < NG * H2) g_pool[i] = 0u;
}

__global__ void k_cnt(const int* __restrict__ dst, int E) {
    int e = blockIdx.x * blockDim.x + threadIdx.x;
    if (e < E) atomicAdd(&g_cnt[dst[e]], 1);
}

__global__ void k_scanA() {          // per-block sums
    __shared__ int s[SB];
    int i = blockIdx.x * SB + threadIdx.x;
    s[threadIdx.x] = (i < Nn) ? g_cnt[i] : 0;
    __syncthreads();
    for (int d = SB / 2; d > 0; d >>= 1) {
        if (threadIdx.x < d) s[threadIdx.x] += s[threadIdx.x + d];
        __syncthreads();
    }
    if (threadIdx.x == 0) g_part[blockIdx.x] = s[0];
}

__global__ void k_scanB() {          // scan of 391 partials (1 block, 512 thr)
    __shared__ int s[512];
    int t = threadIdx.x;
    s[t] = (t < NSB) ? g_part[t] : 0;
    __syncthreads();
    for (int d = 1; d < 512; d <<= 1) {
        int v = (t >= d) ? s[t - d] : 0;
        __syncthreads();
        s[t] += v;
        __syncthreads();
    }
    if (t < NSB) g_part[t] = (t == 0) ? 0 : s[t - 1];   // exclusive offsets
    if (t == 0)  g_row[Nn] = s[NSB - 1];                 // total = E
}

__global__ void k_scanC() {          // per-block exclusive scan + dinv
    __shared__ int s[SB];
    int t = threadIdx.x;
    int i = blockIdx.x * SB + t;
    int c = (i < Nn) ? g_cnt[i] : 0;
    s[t] = c;
    __syncthreads();
    for (int d = 1; d < SB; d <<= 1) {
        int v = (t >= d) ? s[t - d] : 0;
        __syncthreads();
        s[t] += v;
        __syncthreads();
    }
    if (i < Nn) {
        int excl = g_part[blockIdx.x] + s[t] - c;
        g_row[i]  = excl;
        g_cur[i]  = excl;
        g_dinv[i] = rsqrtf((float)(c + 1));   // self-loop included
    }
}

__global__ void k_fill(const int* __restrict__ src, const int* __restrict__ dst, int E) {
    int e = blockIdx.x * blockDim.x + threadIdx.x;
    if (e < E) {
        int p = atomicAdd(&g_cur[dst[e]], 1);
        g_srt[p] = src[e];
    }
}

// ---------------- GEMM 1: h1 = (x @ W1) * dinv  (64-row tiles, 8 rows/thread)
__global__ void k_gemm1(const float* __restrict__ x, const float* __restrict__ W1) {
    __shared__ float ws[FIN * H1];     // 16 KB
    __shared__ float xs[64 * FIN];     // 32 KB
    const int tid = threadIdx.x;
    for (int i = tid; i < FIN * H1; i += 256) ws[i] = W1[i];
    const int base = blockIdx.x * 64;
    for (int i = tid; i < 64 * (FIN / 4); i += 256) {   // 2048 float4
        int r = i >> 5, f = i & 31;
        int row = base + r;
        float4 v = make_float4(0.f, 0.f, 0.f, 0.f);
        if (row < Nn) v = *(const float4*)(x + (size_t)row * FIN + f * 4);
        *(float4*)(xs + r * FIN + f * 4) = v;
    }
    __syncthreads();
    const int cc = tid & 31, ry = tid >> 5;
    float acc[8] = {0.f, 0.f, 0.f, 0.f, 0.f, 0.f, 0.f, 0.f};
    #pragma unroll 4
    for (int k4 = 0; k4 < FIN / 4; k4++) {
        float w0 = ws[(k4 * 4 + 0) * H1 + cc];
        float w1 = ws[(k4 * 4 + 1) * H1 + cc];
        float w2 = ws[(k4 * 4 + 2) * H1 + cc];
        float w3 = ws[(k4 * 4 + 3) * H1 + cc];
        #pragma unroll
        for (int r = 0; r < 8; r++) {
            float4 xv = *(const float4*)(xs + (ry * 8 + r) * FIN + k4 * 4);
            acc[r] += xv.x * w0 + xv.y * w1 + xv.z * w2 + xv.w * w3;
        }
    }
    #pragma unroll
    for (int r = 0; r < 8; r++) {
        int row = base + ry * 8 + r;
        if (row < Nn) g_h1[(size_t)row * H1 + cc] = acc[r] * g_dinv[row];
    }
}

// ---------------- gather 1: a1 = dinv_d * (sum_src h1s + h1s_own) -----------
__global__ void k_gather1() {
    int tid = blockIdx.x * 256 + threadIdx.x;
    int node = tid >> 3, c = tid & 7;
    if (node >= Nn) return;
    int beg = g_row[node], end = g_row[node + 1];
    const float* __restrict__ hp = g_h1;
    float4 acc = *(const float4*)(hp + (size_t)node * H1 + c * 4);   // self-loop
    int e = beg;
    for (; e + 4 <= end; e += 4) {
        int s0 = g_srt[e], s1 = g_srt[e + 1], s2 = g_srt[e + 2], s3 = g_srt[e + 3];
        float4 v0 = *(const float4*)(hp + (size_t)s0 * H1 + c * 4);
        float4 v1 = *(const float4*)(hp + (size_t)s1 * H1 + c * 4);
        float4 v2 = *(const float4*)(hp + (size_t)s2 * H1 + c * 4);
        float4 v3 = *(const float4*)(hp + (size_t)s3 * H1 + c * 4);
        acc.x += (v0.x + v1.x) + (v2.x + v3.x);
        acc.y += (v0.y + v1.y) + (v2.y + v3.y);
        acc.z += (v0.z + v1.z) + (v2.z + v3.z);
        acc.w += (v0.w + v1.w) + (v2.w + v3.w);
    }
    for (; e < end; e++) {
        int s = g_srt[e];
        float4 v = *(const float4*)(hp + (size_t)s * H1 + c * 4);
        acc.x += v.x; acc.y += v.y; acc.z += v.z; acc.w += v.w;
    }
    float di = g_dinv[node];
    float4 o = make_float4(acc.x * di, acc.y * di, acc.z * di, acc.w * di);
    *(float4*)(g_a1 + (size_t)node * H1 + c * 4) = o;
}

// ---------------- GEMM 2: h2 = (leaky(a1+b1) @ W2) * dinv  (32-row tiles) ---
__global__ void k_gemm2(const float* __restrict__ W2, const float* __restrict__ b1) {
    __shared__ float ws[H1 * H2];    // 8 KB
    __shared__ float bs[H1];
    __shared__ float xs[32 * H1];    // 4 KB
    const int tid = threadIdx.x;
    for (int i = tid; i < H1 * H2; i += 256) ws[i] = W2[i];
    if (tid < H1) bs[tid] = b1[tid];
    __syncthreads();
    const int base = blockIdx.x * 32;
    for (int i = tid; i < 32 * H1; i += 256) {
        int r = i >> 5, k = i & 31;
        int row = base + r;
        float v = (row < Nn) ? g_a1[(size_t)row * H1 + k] + bs[k] : 0.f;
        xs[r * H1 + k] = leaky(v);
    }
    __syncthreads();
    const int cc = tid & 63, ry = tid >> 6;   // ry 0..3, 8 rows each
    float acc[8] = {0.f, 0.f, 0.f, 0.f, 0.f, 0.f, 0.f, 0.f};
    #pragma unroll
    for (int k4 = 0; k4 < H1 / 4; k4++) {
        float w0 = ws[(k4 * 4 + 0) * H2 + cc];
        float w1 = ws[(k4 * 4 + 1) * H2 + cc];
        float w2 = ws[(k4 * 4 + 2) * H2 + cc];
        float w3 = ws[(k4 * 4 + 3) * H2 + cc];
        #pragma unroll
        for (int r = 0; r < 8; r++) {
            float4 xv = *(const float4*)(xs + (ry * 8 + r) * H1 + k4 * 4);
            acc[r] += xv.x * w0 + xv.y * w1 + xv.z * w2 + xv.w * w3;
        }
    }
    #pragma unroll
    for (int r = 0; r < 8; r++) {
        int row = base + ry * 8 + r;
        if (row < Nn) g_h2[(size_t)row * H2 + cc] = acc[r] * g_dinv[row];
    }
}

// ---------------- gather 2 fused with global max pool -----------------------
__global__ void k_gather2(const int* __restrict__ batch, const float* __restrict__ b2) {
    int tid = blockIdx.x * 256 + threadIdx.x;
    int node = tid >> 4, c = tid & 15;
    if (node >= Nn) return;
    int beg = g_row[node], end = g_row[node + 1];
    const float* __restrict__ hp = g_h2;
    float4 acc = *(const float4*)(hp + (size_t)node * H2 + c * 4);   // self-loop
    int e = beg;
    for (; e + 4 <= end; e += 4) {
        int s0 = g_srt[e], s1 = g_srt[e + 1], s2 = g_srt[e + 2], s3 = g_srt[e + 3];
        float4 v0 = *(const float4*)(hp + (size_t)s0 * H2 + c * 4);
        float4 v1 = *(const float4*)(hp + (size_t)s1 * H2 + c * 4);
        float4 v2 = *(const float4*)(hp + (size_t)s2 * H2 + c * 4);
        float4 v3 = *(const float4*)(hp + (size_t)s3 * H2 + c * 4);
        acc.x += (v0.x + v1.x) + (v2.x + v3.x);
        acc.y += (v0.y + v1.y) + (v2.y + v3.y);
        acc.z += (v0.z + v1.z) + (v2.z + v3.z);
        acc.w += (v0.w + v1.w) + (v2.w + v3.w);
    }
    for (; e < end; e++) {
        int s = g_srt[e];
        float4 v = *(const float4*)(hp + (size_t)s * H2 + c * 4);
        acc.x += v.x; acc.y += v.y; acc.z += v.z; acc.w += v.w;
    }
    float di = g_dinv[node];
    float4 bb = *(const float4*)(b2 + c * 4);
    unsigned* pool = g_pool + (size_t)batch[node] * H2 + c * 4;
    atomicMax(pool + 0, enc_f(acc.x * di + bb.x));
    atomicMax(pool + 1, enc_f(acc.y * di + bb.y));
    atomicMax(pool + 2, enc_f(acc.z * di + bb.z));
    atomicMax(pool + 3, enc_f(acc.w * di + bb.w));
}

// ---------------- MLP head ---------------------------------------------------
__global__ void k_mlp(const float* __restrict__ l1W, const float* __restrict__ l1b,
                      const float* __restrict__ l2W, const float* __restrict__ l2b,
                      const float* __restrict__ l3W, const float* __restrict__ l3b,
                      float* __restrict__ out) {
    __shared__ float gv[H2], z1[128], z2[64];
    const int g = blockIdx.x, t = threadIdx.x;
    if (t < H2) gv[t] = dec_f(g_pool[g * H2 + t]);
    __syncthreads();
    {
        float acc = l1b[t];
        #pragma unroll 8
        for (int k = 0; k < 64; k++) acc += gv[k] * l1W[k * 128 + t];
        z1[t] = leaky(acc);
    }
    __syncthreads();
    if (t < 64) {
        float acc = l2b[t];
        #pragma unroll 8
        for (int k = 0; k < 128; k++) acc += z1[k] * l2W[k * 64 + t];
        z2[t] = leaky(acc);
    }
    __syncthreads();
    if (t < 64) {
        float acc = l3b[t];
        #pragma unroll 8
        for (int k = 0; k < 64; k++) acc += z2[k] * l3W[k * 64 + t];
        out[g * 64 + t] = acc;
    }
}

// ---------------- launch ------------------------------------------------------
extern "C" void kernel_launch(void* const* d_in, const int* in_sizes, int n_in,
                              void* d_out, int out_size) {
    const float* x    = (const float*)d_in[0];
    const int*   ei   = (const int*)  d_in[1];
    const int*   batch= (const int*)  d_in[2];
    const float* W1   = (const float*)d_in[3];
    const float* b1   = (const float*)d_in[4];
    const float* W2   = (const float*)d_in[5];
    const float* b2   = (const float*)d_in[6];
    const float* l1W  = (const float*)d_in[7];
    const float* l1b  = (const float*)d_in[8];
    const float* l2W  = (const float*)d_in[9];
    const float* l2b  = (const float*)d_in[10];
    const float* l3W  = (const float*)d_in[11];
    const float* l3b  = (const float*)d_in[12];
    float* out = (float*)d_out;

    const int E = in_sizes[1] / 2;
    const int* src = ei;
    const int* dst = ei + E;

    k_init <<<(Nn + 255) / 256, 256>>>();
    k_cnt  <<<(E + 255) / 256, 256>>>(dst, E);
    k_scanA<<<NSB, SB>>>();
    k_scanB<<<1, 512>>>();
    k_scanC<<<NSB, SB>>>();
    k_fill <<<(E + 255) / 256, 256>>>(src, dst, E);
    k_gemm1<<<(Nn + 63) / 64, 256>>>(x, W1);
    k_gather1<<<(Nn * 8 + 255) / 256, 256>>>();
    k_gemm2<<<(Nn + 31) / 32, 256>>>(W2, b1);
    k_gather2<<<(Nn * 16 + 255) / 256, 256>>>(batch, b2);
    k_mlp  <<<NG, 128>>>(l1W, l1b, l2W, l2b, l3W, l3b, out);
}

// round 9
// speedup vs baseline: 1.9303x; 1.3008x over previous
#include <cuda_runtime.h>

#define Nn   100000
#define Ee   3200000
#define FIN  128
#define H1   32
#define H2   64
#define NG   256

#define SB   256
#define NSB  ((Nn + SB - 1) / SB)   // 391

// ---------------- scratch ---------------------------------------------------
__device__ int      g_cnt[Nn];
__device__ int      g_row[Nn + 1];
__device__ int      g_cur[Nn];
__device__ int      g_srt[Ee];         // edge srcs sorted by dst
__device__ int      g_part[NSB];
__device__ float    g_dinv[Nn];
__device__ float    g_h1 [Nn * H1];    // (x@W1) * dinv
__device__ float    g_x2 [Nn * H1];    // leaky(a1+b1) * dinv
__device__ float    g_y  [Nn * H1];    // layer-2 aggregate (32-dim, pre-W2)
__device__ unsigned g_pool[NG * H2];   // encoded segment max

// ---------------- helpers ---------------------------------------------------
__device__ __forceinline__ float leaky(float v) { return v > 0.f ? v : 0.1f * v; }
__device__ __forceinline__ unsigned enc_f(float f) {
    unsigned u = __float_as_uint(f);
    return (u & 0x80000000u) ? ~u : (u | 0x80000000u);
}
__device__ __forceinline__ float dec_f(unsigned u) {
    return __uint_as_float((u & 0x80000000u) ? (u & 0x7fffffffu) : ~u);
}

// ---------------- CSR build --------------------------------------------------
__global__ void k_init() {
    int i = blockIdx.x * blockDim.x + threadIdx.x;
    if (i < Nn)      g_cnt[i]  = 0;
    if (i < NG * H2) g_pool[i] = 0u;
}

__global__ void k_cnt(const int* __restrict__ dst, int E) {
    int e = blockIdx.x * blockDim.x + threadIdx.x;
    if (e < E) atomicAdd(&g_cnt[dst[e]], 1);
}

__global__ void k_scanA() {          // per-block sums
    __shared__ int s[SB];
    int i = blockIdx.x * SB + threadIdx.x;
    s[threadIdx.x] = (i < Nn) ? g_cnt[i] : 0;
    __syncthreads();
    for (int d = SB / 2; d > 0; d >>= 1) {
        if (threadIdx.x < d) s[threadIdx.x] += s[threadIdx.x + d];
        __syncthreads();
    }
    if (threadIdx.x == 0) g_part[blockIdx.x] = s[0];
}

__global__ void k_scanB() {          // scan of NSB partials (1 block)
    __shared__ int s[512];
    int t = threadIdx.x;
    s[t] = (t < NSB) ? g_part[t] : 0;
    __syncthreads();
    for (int d = 1; d < 512; d <<= 1) {
        int v = (t >= d) ? s[t - d] : 0;
        __syncthreads();
        s[t] += v;
        __syncthreads();
    }
    if (t < NSB) g_part[t] = (t == 0) ? 0 : s[t - 1];   // exclusive offsets
    if (t == 0)  g_row[Nn] = s[NSB - 1];
}

__global__ void k_scanC() {          // per-block exclusive scan + dinv
    __shared__ int s[SB];
    int t = threadIdx.x;
    int i = blockIdx.x * SB + t;
    int c = (i < Nn) ? g_cnt[i] : 0;
    s[t] = c;
    __syncthreads();
    for (int d = 1; d < SB; d <<= 1) {
        int v = (t >= d) ? s[t - d] : 0;
        __syncthreads();
        s[t] += v;
        __syncthreads();
    }
    if (i < Nn) {
        int excl = g_part[blockIdx.x] + s[t] - c;
        g_row[i]  = excl;
        g_cur[i]  = excl;
        g_dinv[i] = rsqrtf((float)(c + 1));   // self-loop included
    }
}

__global__ void k_fill(const int* __restrict__ src, const int* __restrict__ dst, int E) {
    int e = blockIdx.x * blockDim.x + threadIdx.x;
    if (e < E) {
        int p = atomicAdd(&g_cur[dst[e]], 1);
        g_srt[p] = src[e];
    }
}

// ---------------- GEMM 1: h1 = (x @ W1) * dinv  (64-row tiles, 8 rows/thread)
__global__ void k_gemm1(const float* __restrict__ x, const float* __restrict__ W1) {
    __shared__ float ws[FIN * H1];     // 16 KB
    __shared__ float xs[64 * FIN];     // 32 KB
    const int tid = threadIdx.x;
    for (int i = tid; i < FIN * H1; i += 256) ws[i] = W1[i];
    const int base = blockIdx.x * 64;
    for (int i = tid; i < 64 * (FIN / 4); i += 256) {
        int r = i >> 5, f = i & 31;
        int row = base + r;
        float4 v = make_float4(0.f, 0.f, 0.f, 0.f);
        if (row < Nn) v = *(const float4*)(x + (size_t)row * FIN + f * 4);
        *(float4*)(xs + r * FIN + f * 4) = v;
    }
    __syncthreads();
    const int cc = tid & 31, ry = tid >> 5;
    float acc[8] = {0.f, 0.f, 0.f, 0.f, 0.f, 0.f, 0.f, 0.f};
    #pragma unroll 4
    for (int k4 = 0; k4 < FIN / 4; k4++) {
        float w0 = ws[(k4 * 4 + 0) * H1 + cc];
        float w1 = ws[(k4 * 4 + 1) * H1 + cc];
        float w2 = ws[(k4 * 4 + 2) * H1 + cc];
        float w3 = ws[(k4 * 4 + 3) * H1 + cc];
        #pragma unroll
        for (int r = 0; r < 8; r++) {
            float4 xv = *(const float4*)(xs + (ry * 8 + r) * FIN + k4 * 4);
            acc[r] += xv.x * w0 + xv.y * w1 + xv.z * w2 + xv.w * w3;
        }
    }
    #pragma unroll
    for (int r = 0; r < 8; r++) {
        int row = base + ry * 8 + r;
        if (row < Nn) g_h1[(size_t)row * H1 + cc] = acc[r] * g_dinv[row];
    }
}

// ---------------- generic 32-dim CSR gather (8 lanes/node, shfl-shared idx) --
// MODE 0: in=g_h1, out=g_x2, out = leaky(acc*dinv + b1) * dinv
// MODE 1: in=g_x2, out=g_y,  out = acc*dinv
// (buffers selected in DEVICE code — __device__ symbols are not valid host args)
template<int MODE>
__global__ void k_gather(const float* __restrict__ b1) {
    const float* __restrict__ in  = (MODE == 0) ? g_h1 : g_x2;
    float*       __restrict__ outp = (MODE == 0) ? g_x2 : g_y;
    int tid = blockIdx.x * 256 + threadIdx.x;
    int node = tid >> 3, c = tid & 7;
    if (node >= Nn) return;
    const int lane = threadIdx.x & 31;
    const unsigned mask = 0xFFu << (lane & 24);   // this 8-lane group
    int beg = g_row[node], end = g_row[node + 1];
    float4 acc = *(const float4*)(in + (size_t)node * H1 + c * 4);   // self
    for (int e = beg; e < end; e += 8) {
        int myidx = (e + c < end) ? g_srt[e + c] : 0;
        int m = end - e; if (m > 8) m = 8;
        #pragma unroll 8
        for (int j = 0; j < 8; j++) {
            if (j >= m) break;
            int s = __shfl_sync(mask, myidx, j, 8);
            float4 v = *(const float4*)(in + (size_t)s * H1 + c * 4);
            acc.x += v.x; acc.y += v.y; acc.z += v.z; acc.w += v.w;
        }
    }
    float di = g_dinv[node];
    float4 o;
    if (MODE == 0) {
        float4 bb = *(const float4*)(b1 + c * 4);
        o.x = leaky(acc.x * di + bb.x) * di;
        o.y = leaky(acc.y * di + bb.y) * di;
        o.z = leaky(acc.z * di + bb.z) * di;
        o.w = leaky(acc.w * di + bb.w) * di;
    } else {
        o = make_float4(acc.x * di, acc.y * di, acc.z * di, acc.w * di);
    }
    *(float4*)(outp + (size_t)node * H1 + c * 4) = o;
}

// ---------------- GEMM 3 fused with max pool: pool = max(y @ W2 + b2) --------
__global__ void k_gemm3(const float* __restrict__ W2, const float* __restrict__ b2,
                        const int* __restrict__ batch) {
    __shared__ float ws[H1 * H2];    // 8 KB
    __shared__ float xs[32 * H1];    // 4 KB
    const int tid = threadIdx.x;
    for (int i = tid; i < H1 * H2; i += 256) ws[i] = W2[i];
    const int base = blockIdx.x * 32;
    for (int i = tid; i < 32 * (H1 / 4); i += 256) {
        int r = i >> 3, f = i & 7;
        int row = base + r;
        float4 v = make_float4(0.f, 0.f, 0.f, 0.f);
        if (row < Nn) v = *(const float4*)(g_y + (size_t)row * H1 + f * 4);
        *(float4*)(xs + r * H1 + f * 4) = v;
    }
    __syncthreads();
    const int cc = tid & 63, ry = tid >> 6;   // ry 0..3, 8 rows each
    float acc[8] = {0.f, 0.f, 0.f, 0.f, 0.f, 0.f, 0.f, 0.f};
    #pragma unroll
    for (int k4 = 0; k4 < H1 / 4; k4++) {
        float w0 = ws[(k4 * 4 + 0) * H2 + cc];
        float w1 = ws[(k4 * 4 + 1) * H2 + cc];
        float w2 = ws[(k4 * 4 + 2) * H2 + cc];
        float w3 = ws[(k4 * 4 + 3) * H2 + cc];
        #pragma unroll
        for (int r = 0; r < 8; r++) {
            float4 xv = *(const float4*)(xs + (ry * 8 + r) * H1 + k4 * 4);
            acc[r] += xv.x * w0 + xv.y * w1 + xv.z * w2 + xv.w * w3;
        }
    }
    // epilogue: add bias, per-thread run-max over consecutive rows, atomicMax per run
    const float bb = b2[cc];
    int   curb = -1;
    float best = 0.f;
    #pragma unroll
    for (int r = 0; r < 8; r++) {
        int row = base + ry * 8 + r;
        if (row >= Nn) break;
        int   bt = batch[row];
        float v  = acc[r] + bb;
        if (bt != curb) {
            if (curb >= 0) atomicMax(&g_pool[(size_t)curb * H2 + cc], enc_f(best));
            curb = bt; best = v;
        } else if (v > best) best = v;
    }
    if (curb >= 0) atomicMax(&g_pool[(size_t)curb * H2 + cc], enc_f(best));
}

// ---------------- MLP head ---------------------------------------------------
__global__ void k_mlp(const float* __restrict__ l1W, const float* __restrict__ l1b,
                      const float* __restrict__ l2W, const float* __restrict__ l2b,
                      const float* __restrict__ l3W, const float* __restrict__ l3b,
                      float* __restrict__ out) {
    __shared__ float gv[H2], z1[128], z2[64];
    const int g = blockIdx.x, t = threadIdx.x;
    if (t < H2) gv[t] = dec_f(g_pool[g * H2 + t]);
    __syncthreads();
    {
        float acc = l1b[t];
        #pragma unroll 8
        for (int k = 0; k < 64; k++) acc += gv[k] * l1W[k * 128 + t];
        z1[t] = leaky(acc);
    }
    __syncthreads();
    if (t < 64) {
        float acc = l2b[t];
        #pragma unroll 8
        for (int k = 0; k < 128; k++) acc += z1[k] * l2W[k * 64 + t];
        z2[t] = leaky(acc);
    }
    __syncthreads();
    if (t < 64) {
        float acc = l3b[t];
        #pragma unroll 8
        for (int k = 0; k < 64; k++) acc += z2[k] * l3W[k * 64 + t];
        out[g * 64 + t] = acc;
    }
}

// ---------------- launch ------------------------------------------------------
extern "C" void kernel_launch(void* const* d_in, const int* in_sizes, int n_in,
                              void* d_out, int out_size) {
    const float* x    = (const float*)d_in[0];
    const int*   ei   = (const int*)  d_in[1];
    const int*   batch= (const int*)  d_in[2];
    const float* W1   = (const float*)d_in[3];
    const float* b1   = (const float*)d_in[4];
    const float* W2   = (const float*)d_in[5];
    const float* b2   = (const float*)d_in[6];
    const float* l1W  = (const float*)d_in[7];
    const float* l1b  = (const float*)d_in[8];
    const float* l2W  = (const float*)d_in[9];
    const float* l2b  = (const float*)d_in[10];
    const float* l3W  = (const float*)d_in[11];
    const float* l3b  = (const float*)d_in[12];
    float* out = (float*)d_out;

    const int E = in_sizes[1] / 2;
    const int* src = ei;
    const int* dst = ei + E;

    k_init <<<(Nn + 255) / 256, 256>>>();
    k_cnt  <<<(E + 255) / 256, 256>>>(dst, E);
    k_scanA<<<NSB, SB>>>();
    k_scanB<<<1, 512>>>();
    k_scanC<<<NSB, SB>>>();
    k_fill <<<(E + 255) / 256, 256>>>(src, dst, E);
    k_gemm1<<<(Nn + 63) / 64, 256>>>(x, W1);
    k_gather<0><<<(Nn * 8 + 255) / 256, 256>>>(b1);
    k_gather<1><<<(Nn * 8 + 255) / 256, 256>>>(b1);
    k_gemm3<<<(Nn + 31) / 32, 256>>>(W2, b2, batch);
    k_mlp  <<<NG, 128>>>(l1W, l1b, l2W, l2b, l3W, l3b, out);
}

// round 10
// speedup vs baseline: 2.1178x; 1.0971x over previous
#include <cuda_runtime.h>

#define Nn   100000
#define Ee   3200000
#define FIN  128
#define H1   32
#define H2   64
#define NG   256

#define SB    256
#define NSB   ((Nn + SB - 1) / SB)       // 391
#define SRTSZ (Ee + 8 * Nn)              // padded CSR capacity

// ---------------- scratch ---------------------------------------------------
__device__ int      g_cnt[Nn];
__device__ int      g_row[Nn + 1];        // padded offsets
__device__ int      g_cur[Nn];
__device__ int      g_srt[SRTSZ];         // srcs sorted by dst, padded w/ Nn
__device__ int      g_part[NSB];          // padded per-block sums
__device__ float    g_dinv[Nn];
__device__ float    g_h1 [(Nn + 1) * H1]; // (x@W1)*dinv ; row Nn = zeros
__device__ float    g_x2 [(Nn + 1) * H1]; // leaky(a1+b1)*dinv ; row Nn = zeros
__device__ unsigned g_pool[NG * H2];      // encoded segment max

// ---------------- helpers ---------------------------------------------------
__device__ __forceinline__ float leaky(float v) { return v > 0.f ? v : 0.1f * v; }
__device__ __forceinline__ unsigned enc_f(float f) {
    unsigned u = __float_as_uint(f);
    return (u & 0x80000000u) ? ~u : (u | 0x80000000u);
}
__device__ __forceinline__ float dec_f(unsigned u) {
    return __uint_as_float((u & 0x80000000u) ? (u & 0x7fffffffu) : ~u);
}
#define ADDX2(acc, v) asm("add.rn.f32x2 %0, %0, %1;" : "+l"(acc) : "l"(v))
__device__ __forceinline__ void unpk(unsigned long long a, float& lo, float& hi) {
    asm("mov.b64 {%0,%1}, %2;" : "=f"(lo), "=f"(hi) : "l"(a));
}

// ---------------- CSR build --------------------------------------------------
__global__ void k_init() {
    int i = blockIdx.x * blockDim.x + threadIdx.x;
    if (i < Nn)      g_cnt[i]  = 0;
    if (i < NG * H2) g_pool[i] = 0u;
    if (i < H1) {                       // zero the dummy rows
        g_h1[Nn * H1 + i] = 0.f;
        g_x2[Nn * H1 + i] = 0.f;
    }
}

__global__ void k_cnt(const int* __restrict__ dst, int E4) {
    int t = blockIdx.x * blockDim.x + threadIdx.x;
    if (t < E4) {
        int4 d = *(const int4*)(dst + t * 4);
        atomicAdd(&g_cnt[d.x], 1);
        atomicAdd(&g_cnt[d.y], 1);
        atomicAdd(&g_cnt[d.z], 1);
        atomicAdd(&g_cnt[d.w], 1);
    }
}

__global__ void k_scanA() {             // padded per-block sums
    __shared__ int s[SB];
    int i = blockIdx.x * SB + threadIdx.x;
    int c = (i < Nn) ? g_cnt[i] : 0;
    s[threadIdx.x] = (c + 7) & ~7;
    __syncthreads();
    for (int d = SB / 2; d > 0; d >>= 1) {
        if (threadIdx.x < d) s[threadIdx.x] += s[threadIdx.x + d];
        __syncthreads();
    }
    if (threadIdx.x == 0) g_part[blockIdx.x] = s[0];
}

__global__ void k_scanC() {             // offset reduce + local scan + pad fill
    __shared__ int s[SB];
    __shared__ int off_sh;
    const int t = threadIdx.x, b = blockIdx.x;
    int p = 0;
    for (int i = t; i < b; i += SB) p += g_part[i];
    s[t] = p; __syncthreads();
    for (int d = SB / 2; d > 0; d >>= 1) {
        if (t < d) s[t] += s[t + d];
        __syncthreads();
    }
    if (t == 0) off_sh = s[0];
    __syncthreads();
    const int i = b * SB + t;
    const int c  = (i < Nn) ? g_cnt[i] : 0;
    const int pc = (c + 7) & ~7;
    s[t] = pc; __syncthreads();
    for (int d = 1; d < SB; d <<= 1) {   // inclusive scan
        int v = (t >= d) ? s[t - d] : 0;
        __syncthreads();
        s[t] += v;
        __syncthreads();
    }
    if (i < Nn) {
        int excl = off_sh + s[t] - pc;
        g_row[i]  = excl;
        g_cur[i]  = excl;
        g_dinv[i] = rsqrtf((float)(c + 1));
        for (int k = c; k < pc; k++) g_srt[excl + k] = Nn;   // dummy pads
    }
    if (b == NSB - 1 && t == SB - 1) g_row[Nn] = off_sh + s[SB - 1];
}

__global__ void k_fill(const int* __restrict__ src, const int* __restrict__ dst, int E4) {
    int t = blockIdx.x * blockDim.x + threadIdx.x;
    if (t < E4) {
        int4 sv = *(const int4*)(src + t * 4);
        int4 dv = *(const int4*)(dst + t * 4);
        g_srt[atomicAdd(&g_cur[dv.x], 1)] = sv.x;
        g_srt[atomicAdd(&g_cur[dv.y], 1)] = sv.y;
        g_srt[atomicAdd(&g_cur[dv.z], 1)] = sv.z;
        g_srt[atomicAdd(&g_cur[dv.w], 1)] = sv.w;
    }
}

// ---------------- GEMM 1: h1 = (x @ W1) * dinv -------------------------------
__global__ void k_gemm1(const float* __restrict__ x, const float* __restrict__ W1) {
    __shared__ float ws[FIN * H1];     // 16 KB
    __shared__ float xs[64 * FIN];     // 32 KB
    const int tid = threadIdx.x;
    for (int i = tid; i < FIN * H1; i += 256) ws[i] = W1[i];
    const int base = blockIdx.x * 64;
    for (int i = tid; i < 64 * (FIN / 4); i += 256) {
        int r = i >> 5, f = i & 31;
        int row = base + r;
        float4 v = make_float4(0.f, 0.f, 0.f, 0.f);
        if (row < Nn) v = *(const float4*)(x + (size_t)row * FIN + f * 4);
        *(float4*)(xs + r * FIN + f * 4) = v;
    }
    __syncthreads();
    const int cc = tid & 31, ry = tid >> 5;
    float acc[8] = {0.f, 0.f, 0.f, 0.f, 0.f, 0.f, 0.f, 0.f};
    #pragma unroll 4
    for (int k4 = 0; k4 < FIN / 4; k4++) {
        float w0 = ws[(k4 * 4 + 0) * H1 + cc];
        float w1 = ws[(k4 * 4 + 1) * H1 + cc];
        float w2 = ws[(k4 * 4 + 2) * H1 + cc];
        float w3 = ws[(k4 * 4 + 3) * H1 + cc];
        #pragma unroll
        for (int r = 0; r < 8; r++) {
            float4 xv = *(const float4*)(xs + (ry * 8 + r) * FIN + k4 * 4);
            acc[r] += xv.x * w0 + xv.y * w1 + xv.z * w2 + xv.w * w3;
        }
    }
    #pragma unroll
    for (int r = 0; r < 8; r++) {
        int row = base + ry * 8 + r;
        if (row < Nn) g_h1[(size_t)row * H1 + cc] = acc[r] * g_dinv[row];
    }
}

// gather core: 8 lanes/node, 4 dims/lane, packed f32x2 accumulation.
// neighbor lists padded to multiples of 8 with dummy node Nn (zero row).
__device__ __forceinline__ void gather32(const float* __restrict__ in, int node, int c,
                                         unsigned long long& a01, unsigned long long& a23) {
    const ulonglong2* __restrict__ self =
        (const ulonglong2*)(in + (size_t)node * H1 + c * 4);
    ulonglong2 sv = *self;
    a01 = sv.x; a23 = sv.y;
    const int beg = g_row[node], end = g_row[node + 1];
    for (int e = beg; e < end; e += 8) {
        int4 ia = *(const int4*)(g_srt + e);
        int4 ib = *(const int4*)(g_srt + e + 4);
        ulonglong2 v;
        v = *(const ulonglong2*)(in + (size_t)ia.x * H1 + c * 4); ADDX2(a01, v.x); ADDX2(a23, v.y);
        v = *(const ulonglong2*)(in + (size_t)ia.y * H1 + c * 4); ADDX2(a01, v.x); ADDX2(a23, v.y);
        v = *(const ulonglong2*)(in + (size_t)ia.z * H1 + c * 4); ADDX2(a01, v.x); ADDX2(a23, v.y);
        v = *(const ulonglong2*)(in + (size_t)ia.w * H1 + c * 4); ADDX2(a01, v.x); ADDX2(a23, v.y);
        v = *(const ulonglong2*)(in + (size_t)ib.x * H1 + c * 4); ADDX2(a01, v.x); ADDX2(a23, v.y);
        v = *(const ulonglong2*)(in + (size_t)ib.y * H1 + c * 4); ADDX2(a01, v.x); ADDX2(a23, v.y);
        v = *(const ulonglong2*)(in + (size_t)ib.z * H1 + c * 4); ADDX2(a01, v.x); ADDX2(a23, v.y);
        v = *(const ulonglong2*)(in + (size_t)ib.w * H1 + c * 4); ADDX2(a01, v.x); ADDX2(a23, v.y);
    }
}

// ---------------- gather 1: x2 = leaky(agg*dinv + b1) * dinv -----------------
__global__ void k_gather1(const float* __restrict__ b1) {
    int tid = blockIdx.x * 256 + threadIdx.x;
    int node = tid >> 3, c = tid & 7;
    if (node >= Nn) return;
    unsigned long long a01, a23;
    gather32(g_h1, node, c, a01, a23);
    float di = g_dinv[node];
    float f0, f1, f2, f3;
    unpk(a01, f0, f1); unpk(a23, f2, f3);
    float4 bb = *(const float4*)(b1 + c * 4);
    float4 o;
    o.x = leaky(f0 * di + bb.x) * di;
    o.y = leaky(f1 * di + bb.y) * di;
    o.z = leaky(f2 * di + bb.z) * di;
    o.w = leaky(f3 * di + bb.w) * di;
    *(float4*)(g_x2 + (size_t)node * H1 + c * 4) = o;
}

// ---------------- gather 2 fused with GEMM3 + max pool -----------------------
// 32 nodes per 256-thread block: gather tile == gemm tile, y stays in smem.
__global__ void k_gather_gemm3(const float* __restrict__ W2, const float* __restrict__ b2,
                               const int* __restrict__ batch) {
    __shared__ float ws[H1 * H2];     // 8 KB
    __shared__ float ys[32 * H1];     // 4 KB
    const int tid = threadIdx.x;
    for (int i = tid; i < H1 * H2; i += 256) ws[i] = W2[i];
    const int nl = tid >> 3, c = tid & 7;
    const int node = blockIdx.x * 32 + nl;
    if (node < Nn) {
        unsigned long long a01, a23;
        gather32(g_x2, node, c, a01, a23);
        float di = g_dinv[node];
        float f0, f1, f2, f3;
        unpk(a01, f0, f1); unpk(a23, f2, f3);
        ys[nl * H1 + c * 4 + 0] = f0 * di;
        ys[nl * H1 + c * 4 + 1] = f1 * di;
        ys[nl * H1 + c * 4 + 2] = f2 * di;
        ys[nl * H1 + c * 4 + 3] = f3 * di;
    } else {
        ys[nl * H1 + c * 4 + 0] = 0.f; ys[nl * H1 + c * 4 + 1] = 0.f;
        ys[nl * H1 + c * 4 + 2] = 0.f; ys[nl * H1 + c * 4 + 3] = 0.f;
    }
    __syncthreads();
    const int cc = tid & 63, ry = tid >> 6;   // 4 groups x 8 rows
    const int base = blockIdx.x * 32;
    float acc[8] = {0.f, 0.f, 0.f, 0.f, 0.f, 0.f, 0.f, 0.f};
    #pragma unroll
    for (int k4 = 0; k4 < H1 / 4; k4++) {
        float w0 = ws[(k4 * 4 + 0) * H2 + cc];
        float w1 = ws[(k4 * 4 + 1) * H2 + cc];
        float w2 = ws[(k4 * 4 + 2) * H2 + cc];
        float w3 = ws[(k4 * 4 + 3) * H2 + cc];
        #pragma unroll
        for (int r = 0; r < 8; r++) {
            float4 xv = *(const float4*)(ys + (ry * 8 + r) * H1 + k4 * 4);
            acc[r] += xv.x * w0 + xv.y * w1 + xv.z * w2 + xv.w * w3;
        }
    }
    const float bb = b2[cc];
    int   curb = -1;
    float best = 0.f;
    #pragma unroll
    for (int r = 0; r < 8; r++) {
        int row = base + ry * 8 + r;
        if (row >= Nn) break;
        int   bt = batch[row];
        float v  = acc[r] + bb;
        if (bt != curb) {
            if (curb >= 0) atomicMax(&g_pool[(size_t)curb * H2 + cc], enc_f(best));
            curb = bt; best = v;
        } else if (v > best) best = v;
    }
    if (curb >= 0) atomicMax(&g_pool[(size_t)curb * H2 + cc], enc_f(best));
}

// ---------------- MLP head ---------------------------------------------------
__global__ void k_mlp(const float* __restrict__ l1W, const float* __restrict__ l1b,
                      const float* __restrict__ l2W, const float* __restrict__ l2b,
                      const float* __restrict__ l3W, const float* __restrict__ l3b,
                      float* __restrict__ out) {
    __shared__ float gv[H2], z1[128], z2[64];
    const int g = blockIdx.x, t = threadIdx.x;
    if (t < H2) gv[t] = dec_f(g_pool[g * H2 + t]);
    __syncthreads();
    {
        float acc = l1b[t];
        #pragma unroll 8
        for (int k = 0; k < 64; k++) acc += gv[k] * l1W[k * 128 + t];
        z1[t] = leaky(acc);
    }
    __syncthreads();
    if (t < 64) {
        float acc = l2b[t];
        #pragma unroll 8
        for (int k = 0; k < 128; k++) acc += z1[k] * l2W[k * 64 + t];
        z2[t] = leaky(acc);
    }
    __syncthreads();
    if (t < 64) {
        float acc = l3b[t];
        #pragma unroll 8
        for (int k = 0; k < 64; k++) acc += z2[k] * l3W[k * 64 + t];
        out[g * 64 + t] = acc;
    }
}

// ---------------- launch ------------------------------------------------------
extern "C" void kernel_launch(void* const* d_in, const int* in_sizes, int n_in,
                              void* d_out, int out_size) {
    const float* x    = (const float*)d_in[0];
    const int*   ei   = (const int*)  d_in[1];
    const int*   batch= (const int*)  d_in[2];
    const float* W1   = (const float*)d_in[3];
    const float* b1   = (const float*)d_in[4];
    const float* W2   = (const float*)d_in[5];
    const float* b2   = (const float*)d_in[6];
    const float* l1W  = (const float*)d_in[7];
    const float* l1b  = (const float*)d_in[8];
    const float* l2W  = (const float*)d_in[9];
    const float* l2b  = (const float*)d_in[10];
    const float* l3W  = (const float*)d_in[11];
    const float* l3b  = (const float*)d_in[12];
    float* out = (float*)d_out;

    const int E  = in_sizes[1] / 2;
    const int E4 = E / 4;
    const int* src = ei;
    const int* dst = ei + E;

    k_init <<<(Nn + 255) / 256, 256>>>();
    k_cnt  <<<(E4 + 255) / 256, 256>>>(dst, E4);
    k_scanA<<<NSB, SB>>>();
    k_scanC<<<NSB, SB>>>();
    k_fill <<<(E4 + 255) / 256, 256>>>(src, dst, E4);
    k_gemm1<<<(Nn + 63) / 64, 256>>>(x, W1);
    k_gather1<<<(Nn * 8 + 255) / 256, 256>>>(b1);
    k_gather_gemm3<<<(Nn + 31) / 32, 256>>>(W2, b2, batch);
    k_mlp  <<<NG, 128>>>(l1W, l1b, l2W, l2b, l3W, l3b, out);
}

// round 11
// speedup vs baseline: 2.1682x; 1.0238x over previous
#include <cuda_runtime.h>

#define Nn   100000
#define Ee   3200000
#define FIN  128
#define H1   32
#define H2   64
#define NG   256

#define SB    256
#define NSB   ((Nn + SB - 1) / SB)       // 391
#define SRTSZ (Ee + 8 * Nn)              // padded CSR capacity

// ---------------- scratch ---------------------------------------------------
__device__ int      g_cnt[Nn];
__device__ int      g_row[Nn + 1];        // padded offsets
__device__ int      g_cur[Nn];
__device__ int      g_srt[SRTSZ];         // srcs sorted by dst, padded w/ Nn
__device__ int      g_part[NSB];          // padded per-block sums
__device__ float    g_dinv[Nn];
__device__ float    g_h1 [(Nn + 1) * H1]; // (x@W1)*dinv ; row Nn = zeros
__device__ float    g_x2 [(Nn + 1) * H1]; // leaky(a1+b1)*dinv ; row Nn = zeros
__device__ unsigned g_pool[NG * H2];      // encoded segment max

// ---------------- helpers ---------------------------------------------------
__device__ __forceinline__ float leaky(float v) { return v > 0.f ? v : 0.1f * v; }
__device__ __forceinline__ unsigned enc_f(float f) {
    unsigned u = __float_as_uint(f);
    return (u & 0x80000000u) ? ~u : (u | 0x80000000u);
}
__device__ __forceinline__ float dec_f(unsigned u) {
    return __uint_as_float((u & 0x80000000u) ? (u & 0x7fffffffu) : ~u);
}
#define ADDX2(acc, v) asm("add.rn.f32x2 %0, %0, %1;" : "+l"(acc) : "l"(v))
#define FMAX2(acc, a, b) asm("fma.rn.f32x2 %0, %1, %2, %0;" : "+l"(acc) : "l"(a), "l"(b))
__device__ __forceinline__ void unpk(unsigned long long a, float& lo, float& hi) {
    asm("mov.b64 {%0,%1}, %2;" : "=f"(lo), "=f"(hi) : "l"(a));
}
__device__ __forceinline__ unsigned long long pk(float lo, float hi) {
    unsigned long long r;
    asm("mov.b64 %0, {%1,%2};" : "=l"(r) : "f"(lo), "f"(hi));
    return r;
}

// ---------------- CSR build --------------------------------------------------
__global__ void k_init() {
    int i = blockIdx.x * blockDim.x + threadIdx.x;
    if (i < Nn)      g_cnt[i]  = 0;
    if (i < NG * H2) g_pool[i] = 0u;
    if (i < H1) {                       // zero the dummy rows
        g_h1[Nn * H1 + i] = 0.f;
        g_x2[Nn * H1 + i] = 0.f;
    }
}

__global__ void k_cnt(const int* __restrict__ dst, int E4) {
    int t = blockIdx.x * blockDim.x + threadIdx.x;
    if (t < E4) {
        int4 d = *(const int4*)(dst + t * 4);
        atomicAdd(&g_cnt[d.x], 1);
        atomicAdd(&g_cnt[d.y], 1);
        atomicAdd(&g_cnt[d.z], 1);
        atomicAdd(&g_cnt[d.w], 1);
    }
}

__global__ void k_scanA() {             // padded per-block sums
    __shared__ int s[SB];
    int i = blockIdx.x * SB + threadIdx.x;
    int c = (i < Nn) ? g_cnt[i] : 0;
    s[threadIdx.x] = (c + 7) & ~7;
    __syncthreads();
    for (int d = SB / 2; d > 0; d >>= 1) {
        if (threadIdx.x < d) s[threadIdx.x] += s[threadIdx.x + d];
        __syncthreads();
    }
    if (threadIdx.x == 0) g_part[blockIdx.x] = s[0];
}

__global__ void k_scanC() {             // offset reduce + local scan + pad fill
    __shared__ int s[SB];
    __shared__ int off_sh;
    const int t = threadIdx.x, b = blockIdx.x;
    int p = 0;
    for (int i = t; i < b; i += SB) p += g_part[i];
    s[t] = p; __syncthreads();
    for (int d = SB / 2; d > 0; d >>= 1) {
        if (t < d) s[t] += s[t + d];
        __syncthreads();
    }
    if (t == 0) off_sh = s[0];
    __syncthreads();
    const int i = b * SB + t;
    const int c  = (i < Nn) ? g_cnt[i] : 0;
    const int pc = (c + 7) & ~7;
    s[t] = pc; __syncthreads();
    for (int d = 1; d < SB; d <<= 1) {   // inclusive scan
        int v = (t >= d) ? s[t - d] : 0;
        __syncthreads();
        s[t] += v;
        __syncthreads();
    }
    if (i < Nn) {
        int excl = off_sh + s[t] - pc;
        g_row[i]  = excl;
        g_cur[i]  = excl;
        g_dinv[i] = rsqrtf((float)(c + 1));
        for (int k = c; k < pc; k++) g_srt[excl + k] = Nn;   // dummy pads
    }
    if (b == NSB - 1 && t == SB - 1) g_row[Nn] = off_sh + s[SB - 1];
}

__global__ void k_fill(const int* __restrict__ src, const int* __restrict__ dst, int E4) {
    int t = blockIdx.x * blockDim.x + threadIdx.x;
    if (t < E4) {
        int4 sv = *(const int4*)(src + t * 4);
        int4 dv = *(const int4*)(dst + t * 4);
        g_srt[atomicAdd(&g_cur[dv.x], 1)] = sv.x;
        g_srt[atomicAdd(&g_cur[dv.y], 1)] = sv.y;
        g_srt[atomicAdd(&g_cur[dv.z], 1)] = sv.z;
        g_srt[atomicAdd(&g_cur[dv.w], 1)] = sv.w;
    }
}

// ---------------- GEMM 1: h1 = (x @ W1) * dinv  (packed f32x2 FMA) -----------
// acc2[r] = (sum over even-k, sum over odd-k) for (row r, col cc); merged at end.
__global__ void k_gemm1(const float* __restrict__ x, const float* __restrict__ W1) {
    __shared__ unsigned long long wsp[(FIN / 2) * H1];  // 16 KB: [k2][c] pairs
    __shared__ float xs[64 * FIN];                      // 32 KB
    const int tid = threadIdx.x;
    for (int i = tid; i < (FIN / 2) * H1; i += 256) {
        int k2 = i >> 5, c = i & 31;
        wsp[i] = pk(W1[(2 * k2) * H1 + c], W1[(2 * k2 + 1) * H1 + c]);
    }
    const int base = blockIdx.x * 64;
    for (int i = tid; i < 64 * (FIN / 4); i += 256) {
        int r = i >> 5, f = i & 31;
        int row = base + r;
        float4 v = make_float4(0.f, 0.f, 0.f, 0.f);
        if (row < Nn) v = *(const float4*)(x + (size_t)row * FIN + f * 4);
        *(float4*)(xs + r * FIN + f * 4) = v;
    }
    __syncthreads();
    const int cc = tid & 31, ry = tid >> 5;
    unsigned long long acc2[8] = {0ull,0ull,0ull,0ull,0ull,0ull,0ull,0ull};
    #pragma unroll 4
    for (int k4 = 0; k4 < FIN / 4; k4++) {
        unsigned long long w0 = wsp[(2 * k4)     * H1 + cc];
        unsigned long long w1 = wsp[(2 * k4 + 1) * H1 + cc];
        #pragma unroll
        for (int r = 0; r < 8; r++) {
            ulonglong2 xv = *(const ulonglong2*)(xs + (ry * 8 + r) * FIN + k4 * 4);
            FMAX2(acc2[r], xv.x, w0);
            FMAX2(acc2[r], xv.y, w1);
        }
    }
    #pragma unroll
    for (int r = 0; r < 8; r++) {
        int row = base + ry * 8 + r;
        if (row < Nn) {
            float lo, hi; unpk(acc2[r], lo, hi);
            g_h1[(size_t)row * H1 + cc] = (lo + hi) * g_dinv[row];
        }
    }
}

// gather core: 8 lanes/node, 4 dims/lane, packed f32x2 accumulation.
// neighbor lists padded to multiples of 8 with dummy node Nn (zero row).
__device__ __forceinline__ void gather32(const float* __restrict__ in, int node, int c,
                                         unsigned long long& a01, unsigned long long& a23) {
    const ulonglong2* __restrict__ self =
        (const ulonglong2*)(in + (size_t)node * H1 + c * 4);
    ulonglong2 sv = *self;
    a01 = sv.x; a23 = sv.y;
    const int beg = g_row[node], end = g_row[node + 1];
    for (int e = beg; e < end; e += 8) {
        int4 ia = *(const int4*)(g_srt + e);
        int4 ib = *(const int4*)(g_srt + e + 4);
        ulonglong2 v;
        v = *(const ulonglong2*)(in + (size_t)ia.x * H1 + c * 4); ADDX2(a01, v.x); ADDX2(a23, v.y);
        v = *(const ulonglong2*)(in + (size_t)ia.y * H1 + c * 4); ADDX2(a01, v.x); ADDX2(a23, v.y);
        v = *(const ulonglong2*)(in + (size_t)ia.z * H1 + c * 4); ADDX2(a01, v.x); ADDX2(a23, v.y);
        v = *(const ulonglong2*)(in + (size_t)ia.w * H1 + c * 4); ADDX2(a01, v.x); ADDX2(a23, v.y);
        v = *(const ulonglong2*)(in + (size_t)ib.x * H1 + c * 4); ADDX2(a01, v.x); ADDX2(a23, v.y);
        v = *(const ulonglong2*)(in + (size_t)ib.y * H1 + c * 4); ADDX2(a01, v.x); ADDX2(a23, v.y);
        v = *(const ulonglong2*)(in + (size_t)ib.z * H1 + c * 4); ADDX2(a01, v.x); ADDX2(a23, v.y);
        v = *(const ulonglong2*)(in + (size_t)ib.w * H1 + c * 4); ADDX2(a01, v.x); ADDX2(a23, v.y);
    }
}

// ---------------- gather 1: x2 = leaky(agg*dinv + b1) * dinv -----------------
__global__ void k_gather1(const float* __restrict__ b1) {
    int tid = blockIdx.x * 256 + threadIdx.x;
    int node = tid >> 3, c = tid & 7;
    if (node >= Nn) return;
    unsigned long long a01, a23;
    gather32(g_h1, node, c, a01, a23);
    float di = g_dinv[node];
    float f0, f1, f2, f3;
    unpk(a01, f0, f1); unpk(a23, f2, f3);
    float4 bb = *(const float4*)(b1 + c * 4);
    float4 o;
    o.x = leaky(f0 * di + bb.x) * di;
    o.y = leaky(f1 * di + bb.y) * di;
    o.z = leaky(f2 * di + bb.z) * di;
    o.w = leaky(f3 * di + bb.w) * di;
    *(float4*)(g_x2 + (size_t)node * H1 + c * 4) = o;
}

// ---------------- gather 2 fused with GEMM3 (packed FMA) + max pool ----------
// 32 nodes per 256-thread block: gather tile == gemm tile, y stays in smem.
__global__ void k_gather_gemm3(const float* __restrict__ W2, const float* __restrict__ b2,
                               const int* __restrict__ batch) {
    __shared__ unsigned long long wsp[(H1 / 2) * H2];   // 8 KB: [k2][c] pairs
    __shared__ float ys[32 * H1];                       // 4 KB
    const int tid = threadIdx.x;
    for (int i = tid; i < (H1 / 2) * H2; i += 256) {
        int k2 = i >> 6, c = i & 63;
        wsp[i] = pk(W2[(2 * k2) * H2 + c], W2[(2 * k2 + 1) * H2 + c]);
    }
    const int nl = tid >> 3, c = tid & 7;
    const int node = blockIdx.x * 32 + nl;
    if (node < Nn) {
        unsigned long long a01, a23;
        gather32(g_x2, node, c, a01, a23);
        float di = g_dinv[node];
        float f0, f1, f2, f3;
        unpk(a01, f0, f1); unpk(a23, f2, f3);
        ys[nl * H1 + c * 4 + 0] = f0 * di;
        ys[nl * H1 + c * 4 + 1] = f1 * di;
        ys[nl * H1 + c * 4 + 2] = f2 * di;
        ys[nl * H1 + c * 4 + 3] = f3 * di;
    } else {
        ys[nl * H1 + c * 4 + 0] = 0.f; ys[nl * H1 + c * 4 + 1] = 0.f;
        ys[nl * H1 + c * 4 + 2] = 0.f; ys[nl * H1 + c * 4 + 3] = 0.f;
    }
    __syncthreads();
    const int cc = tid & 63, ry = tid >> 6;   // 4 groups x 8 rows
    const int base = blockIdx.x * 32;
    unsigned long long acc2[8] = {0ull,0ull,0ull,0ull,0ull,0ull,0ull,0ull};
    #pragma unroll
    for (int k4 = 0; k4 < H1 / 4; k4++) {
        unsigned long long w0 = wsp[(2 * k4)     * H2 + cc];
        unsigned long long w1 = wsp[(2 * k4 + 1) * H2 + cc];
        #pragma unroll
        for (int r = 0; r < 8; r++) {
            ulonglong2 xv = *(const ulonglong2*)(ys + (ry * 8 + r) * H1 + k4 * 4);
            FMAX2(acc2[r], xv.x, w0);
            FMAX2(acc2[r], xv.y, w1);
        }
    }
    const float bb = b2[cc];
    int   curb = -1;
    float best = 0.f;
    #pragma unroll
    for (int r = 0; r < 8; r++) {
        int row = base + ry * 8 + r;
        if (row >= Nn) break;
        int   bt = batch[row];
        float lo, hi; unpk(acc2[r], lo, hi);
        float v = (lo + hi) + bb;
        if (bt != curb) {
            if (curb >= 0) atomicMax(&g_pool[(size_t)curb * H2 + cc], enc_f(best));
            curb = bt; best = v;
        } else if (v > best) best = v;
    }
    if (curb >= 0) atomicMax(&g_pool[(size_t)curb * H2 + cc], enc_f(best));
}

// ---------------- MLP head ---------------------------------------------------
__global__ void k_mlp(const float* __restrict__ l1W, const float* __restrict__ l1b,
                      const float* __restrict__ l2W, const float* __restrict__ l2b,
                      const float* __restrict__ l3W, const float* __restrict__ l3b,
                      float* __restrict__ out) {
    __shared__ float gv[H2], z1[128], z2[64];
    const int g = blockIdx.x, t = threadIdx.x;
    if (t < H2) gv[t] = dec_f(g_pool[g * H2 + t]);
    __syncthreads();
    {
        float acc = l1b[t];
        #pragma unroll 8
        for (int k = 0; k < 64; k++) acc += gv[k] * l1W[k * 128 + t];
        z1[t] = leaky(acc);
    }
    __syncthreads();
    if (t < 64) {
        float acc = l2b[t];
        #pragma unroll 8
        for (int k = 0; k < 128; k++) acc += z1[k] * l2W[k * 64 + t];
        z2[t] = leaky(acc);
    }
    __syncthreads();
    if (t < 64) {
        float acc = l3b[t];
        #pragma unroll 8
        for (int k = 0; k < 64; k++) acc += z2[k] * l3W[k * 64 + t];
        out[g * 64 + t] = acc;
    }
}

// ---------------- launch ------------------------------------------------------
extern "C" void kernel_launch(void* const* d_in, const int* in_sizes, int n_in,
                              void* d_out, int out_size) {
    const float* x    = (const float*)d_in[0];
    const int*   ei   = (const int*)  d_in[1];
    const int*   batch= (const int*)  d_in[2];
    const float* W1   = (const float*)d_in[3];
    const float* b1   = (const float*)d_in[4];
    const float* W2   = (const float*)d_in[5];
    const float* b2   = (const float*)d_in[6];
    const float* l1W  = (const float*)d_in[7];
    const float* l1b  = (const float*)d_in[8];
    const float* l2W  = (const float*)d_in[9];
    const float* l2b  = (const float*)d_in[10];
    const float* l3W  = (const float*)d_in[11];
    const float* l3b  = (const float*)d_in[12];
    float* out = (float*)d_out;

    const int E  = in_sizes[1] / 2;
    const int E4 = E / 4;
    const int* src = ei;
    const int* dst = ei + E;

    k_init <<<(Nn + 255) / 256, 256>>>();
    k_cnt  <<<(E4 + 255) / 256, 256>>>(dst, E4);
    k_scanA<<<NSB, SB>>>();
    k_scanC<<<NSB, SB>>>();
    k_fill <<<(E4 + 255) / 256, 256>>>(src, dst, E4);
    k_gemm1<<<(Nn + 63) / 64, 256>>>(x, W1);
    k_gather1<<<(Nn * 8 + 255) / 256, 256>>>(b1);
    k_gather_gemm3<<<(Nn + 31) / 32, 256>>>(W2, b2, batch);
    k_mlp  <<<NG, 128>>>(l1W, l1b, l2W, l2b, l3W, l3b, out);
}

// round 12
// speedup vs baseline: 2.3370x; 1.0779x over previous
#include <cuda_runtime.h>

#define Nn   100000
#define Ee   3200000
#define FIN  128
#define H1   32
#define H2   64
#define NG   256

#define SB    256
#define NSB   ((Nn + SB - 1) / SB)       // 391
#define SRTSZ (Ee + 8 * Nn)              // padded CSR capacity

// ---------------- scratch ---------------------------------------------------
__device__ int      g_cnt[Nn];
__device__ int      g_row[Nn + 1];        // padded offsets
__device__ int      g_cur[Nn];
__device__ int      g_srt[SRTSZ];         // srcs sorted by dst, padded w/ Nn
__device__ int      g_part[NSB];          // padded per-block sums
__device__ float    g_dinv[Nn];
__device__ float    g_h1 [(Nn + 1) * H1]; // raw x@W1, then *dinv ; row Nn = 0
__device__ float    g_x2 [(Nn + 1) * H1]; // leaky(a1+b1)*dinv ; row Nn = 0
__device__ unsigned g_pool[NG * H2];      // encoded segment max

// ---------------- helpers ---------------------------------------------------
__device__ __forceinline__ float leaky(float v) { return v > 0.f ? v : 0.1f * v; }
__device__ __forceinline__ unsigned enc_f(float f) {
    unsigned u = __float_as_uint(f);
    return (u & 0x80000000u) ? ~u : (u | 0x80000000u);
}
__device__ __forceinline__ float dec_f(unsigned u) {
    return __uint_as_float((u & 0x80000000u) ? (u & 0x7fffffffu) : ~u);
}
#define ADDX2(acc, v) asm("add.rn.f32x2 %0, %0, %1;" : "+l"(acc) : "l"(v))
#define FMAX2(acc, a, b) asm("fma.rn.f32x2 %0, %1, %2, %0;" : "+l"(acc) : "l"(a), "l"(b))
__device__ __forceinline__ void unpk(unsigned long long a, float& lo, float& hi) {
    asm("mov.b64 {%0,%1}, %2;" : "=f"(lo), "=f"(hi) : "l"(a));
}
__device__ __forceinline__ unsigned long long pk(float lo, float hi) {
    unsigned long long r;
    asm("mov.b64 %0, {%1,%2};" : "=l"(r) : "f"(lo), "f"(hi));
    return r;
}

// ---------------- CSR build (stream 1) ---------------------------------------
__global__ void k_init() {
    int i = blockIdx.x * blockDim.x + threadIdx.x;
    if (i < Nn)      g_cnt[i]  = 0;
    if (i < NG * H2) g_pool[i] = 0u;
    if (i < H1)      g_x2[Nn * H1 + i] = 0.f;   // dummy row for gather2
}

__global__ void k_cnt(const int* __restrict__ dst, int E4) {
    int t = blockIdx.x * blockDim.x + threadIdx.x;
    if (t < E4) {
        int4 d = *(const int4*)(dst + t * 4);
        atomicAdd(&g_cnt[d.x], 1);
        atomicAdd(&g_cnt[d.y], 1);
        atomicAdd(&g_cnt[d.z], 1);
        atomicAdd(&g_cnt[d.w], 1);
    }
}

__global__ void k_scanA() {             // padded per-block sums
    __shared__ int s[SB];
    int i = blockIdx.x * SB + threadIdx.x;
    int c = (i < Nn) ? g_cnt[i] : 0;
    s[threadIdx.x] = (c + 7) & ~7;
    __syncthreads();
    for (int d = SB / 2; d > 0; d >>= 1) {
        if (threadIdx.x < d) s[threadIdx.x] += s[threadIdx.x + d];
        __syncthreads();
    }
    if (threadIdx.x == 0) g_part[blockIdx.x] = s[0];
}

__global__ void k_scanC() {             // offset reduce + local scan + pad fill
    __shared__ int s[SB];
    __shared__ int off_sh;
    const int t = threadIdx.x, b = blockIdx.x;
    int p = 0;
    for (int i = t; i < b; i += SB) p += g_part[i];
    s[t] = p; __syncthreads();
    for (int d = SB / 2; d > 0; d >>= 1) {
        if (t < d) s[t] += s[t + d];
        __syncthreads();
    }
    if (t == 0) off_sh = s[0];
    __syncthreads();
    const int i = b * SB + t;
    const int c  = (i < Nn) ? g_cnt[i] : 0;
    const int pc = (c + 7) & ~7;
    s[t] = pc; __syncthreads();
    for (int d = 1; d < SB; d <<= 1) {   // inclusive scan
        int v = (t >= d) ? s[t - d] : 0;
        __syncthreads();
        s[t] += v;
        __syncthreads();
    }
    if (i < Nn) {
        int excl = off_sh + s[t] - pc;
        g_row[i]  = excl;
        g_cur[i]  = excl;
        g_dinv[i] = rsqrtf((float)(c + 1));
        for (int k = c; k < pc; k++) g_srt[excl + k] = Nn;   // dummy pads
    }
    if (b == NSB - 1 && t == SB - 1) g_row[Nn] = off_sh + s[SB - 1];
}

__global__ void k_fill(const int* __restrict__ src, const int* __restrict__ dst, int E4) {
    int t = blockIdx.x * blockDim.x + threadIdx.x;
    if (t < E4) {
        int4 sv = *(const int4*)(src + t * 4);
        int4 dv = *(const int4*)(dst + t * 4);
        g_srt[atomicAdd(&g_cur[dv.x], 1)] = sv.x;
        g_srt[atomicAdd(&g_cur[dv.y], 1)] = sv.y;
        g_srt[atomicAdd(&g_cur[dv.z], 1)] = sv.z;
        g_srt[atomicAdd(&g_cur[dv.w], 1)] = sv.w;
    }
}

// ---------------- GEMM 1 (stream 2, no CSR dependency): h1_raw = x @ W1 ------
__global__ void k_gemm1(const float* __restrict__ x, const float* __restrict__ W1) {
    __shared__ unsigned long long wsp[(FIN / 2) * H1];  // 16 KB: [k2][c] pairs
    __shared__ float xs[64 * FIN];                      // 32 KB
    const int tid = threadIdx.x;
    for (int i = tid; i < (FIN / 2) * H1; i += 256) {
        int k2 = i >> 5, c = i & 31;
        wsp[i] = pk(W1[(2 * k2) * H1 + c], W1[(2 * k2 + 1) * H1 + c]);
    }
    const int base = blockIdx.x * 64;
    for (int i = tid; i < 64 * (FIN / 4); i += 256) {
        int r = i >> 5, f = i & 31;
        int row = base + r;
        float4 v = make_float4(0.f, 0.f, 0.f, 0.f);
        if (row < Nn) v = *(const float4*)(x + (size_t)row * FIN + f * 4);
        *(float4*)(xs + r * FIN + f * 4) = v;
    }
    __syncthreads();
    const int cc = tid & 31, ry = tid >> 5;
    unsigned long long acc2[8] = {0ull,0ull,0ull,0ull,0ull,0ull,0ull,0ull};
    #pragma unroll 4
    for (int k4 = 0; k4 < FIN / 4; k4++) {
        unsigned long long w0 = wsp[(2 * k4)     * H1 + cc];
        unsigned long long w1 = wsp[(2 * k4 + 1) * H1 + cc];
        #pragma unroll
        for (int r = 0; r < 8; r++) {
            ulonglong2 xv = *(const ulonglong2*)(xs + (ry * 8 + r) * FIN + k4 * 4);
            FMAX2(acc2[r], xv.x, w0);
            FMAX2(acc2[r], xv.y, w1);
        }
    }
    #pragma unroll
    for (int r = 0; r < 8; r++) {
        int row = base + ry * 8 + r;
        if (row < Nn) {
            float lo, hi; unpk(acc2[r], lo, hi);
            g_h1[(size_t)row * H1 + cc] = lo + hi;      // RAW (dinv applied later)
        }
    }
}

// ---------------- after join: h1 *= dinv (and zero dummy row) ----------------
__global__ void k_scale() {
    int t = blockIdx.x * 256 + threadIdx.x;             // one float4 each
    if (t >= (Nn + 1) * (H1 / 4)) return;
    int row = t >> 3;
    float4* p = (float4*)g_h1 + t;
    if (row < Nn) {
        float di = g_dinv[row];
        float4 v = *p;
        *p = make_float4(v.x * di, v.y * di, v.z * di, v.w * di);
    } else {
        *p = make_float4(0.f, 0.f, 0.f, 0.f);
    }
}

// gather core: 8 lanes/node, 4 dims/lane, packed f32x2 accumulation.
// neighbor lists padded to multiples of 8 with dummy node Nn (zero row).
__device__ __forceinline__ void gather32(const float* __restrict__ in, int node, int c,
                                         unsigned long long& a01, unsigned long long& a23) {
    const ulonglong2* __restrict__ self =
        (const ulonglong2*)(in + (size_t)node * H1 + c * 4);
    ulonglong2 sv = *self;
    a01 = sv.x; a23 = sv.y;
    const int beg = g_row[node], end = g_row[node + 1];
    for (int e = beg; e < end; e += 8) {
        int4 ia = *(const int4*)(g_srt + e);
        int4 ib = *(const int4*)(g_srt + e + 4);
        ulonglong2 v;
        v = *(const ulonglong2*)(in + (size_t)ia.x * H1 + c * 4); ADDX2(a01, v.x); ADDX2(a23, v.y);
        v = *(const ulonglong2*)(in + (size_t)ia.y * H1 + c * 4); ADDX2(a01, v.x); ADDX2(a23, v.y);
        v = *(const ulonglong2*)(in + (size_t)ia.z * H1 + c * 4); ADDX2(a01, v.x); ADDX2(a23, v.y);
        v = *(const ulonglong2*)(in + (size_t)ia.w * H1 + c * 4); ADDX2(a01, v.x); ADDX2(a23, v.y);
        v = *(const ulonglong2*)(in + (size_t)ib.x * H1 + c * 4); ADDX2(a01, v.x); ADDX2(a23, v.y);
        v = *(const ulonglong2*)(in + (size_t)ib.y * H1 + c * 4); ADDX2(a01, v.x); ADDX2(a23, v.y);
        v = *(const ulonglong2*)(in + (size_t)ib.z * H1 + c * 4); ADDX2(a01, v.x); ADDX2(a23, v.y);
        v = *(const ulonglong2*)(in + (size_t)ib.w * H1 + c * 4); ADDX2(a01, v.x); ADDX2(a23, v.y);
    }
}

// ---------------- gather 1: x2 = leaky(agg*dinv + b1) * dinv -----------------
__global__ void k_gather1(const float* __restrict__ b1) {
    int tid = blockIdx.x * 256 + threadIdx.x;
    int node = tid >> 3, c = tid & 7;
    if (node >= Nn) return;
    unsigned long long a01, a23;
    gather32(g_h1, node, c, a01, a23);
    float di = g_dinv[node];
    float f0, f1, f2, f3;
    unpk(a01, f0, f1); unpk(a23, f2, f3);
    float4 bb = *(const float4*)(b1 + c * 4);
    float4 o;
    o.x = leaky(f0 * di + bb.x) * di;
    o.y = leaky(f1 * di + bb.y) * di;
    o.z = leaky(f2 * di + bb.z) * di;
    o.w = leaky(f3 * di + bb.w) * di;
    *(float4*)(g_x2 + (size_t)node * H1 + c * 4) = o;
}

// ---------------- gather 2 fused with GEMM3 (packed FMA) + max pool ----------
__global__ void k_gather_gemm3(const float* __restrict__ W2, const float* __restrict__ b2,
                               const int* __restrict__ batch) {
    __shared__ unsigned long long wsp[(H1 / 2) * H2];   // 8 KB: [k2][c] pairs
    __shared__ float ys[32 * H1];                       // 4 KB
    const int tid = threadIdx.x;
    for (int i = tid; i < (H1 / 2) * H2; i += 256) {
        int k2 = i >> 6, c = i & 63;
        wsp[i] = pk(W2[(2 * k2) * H2 + c], W2[(2 * k2 + 1) * H2 + c]);
    }
    const int nl = tid >> 3, c = tid & 7;
    const int node = blockIdx.x * 32 + nl;
    if (node < Nn) {
        unsigned long long a01, a23;
        gather32(g_x2, node, c, a01, a23);
        float di = g_dinv[node];
        float f0, f1, f2, f3;
        unpk(a01, f0, f1); unpk(a23, f2, f3);
        ys[nl * H1 + c * 4 + 0] = f0 * di;
        ys[nl * H1 + c * 4 + 1] = f1 * di;
        ys[nl * H1 + c * 4 + 2] = f2 * di;
        ys[nl * H1 + c * 4 + 3] = f3 * di;
    } else {
        ys[nl * H1 + c * 4 + 0] = 0.f; ys[nl * H1 + c * 4 + 1] = 0.f;
        ys[nl * H1 + c * 4 + 2] = 0.f; ys[nl * H1 + c * 4 + 3] = 0.f;
    }
    __syncthreads();
    const int cc = tid & 63, ry = tid >> 6;   // 4 groups x 8 rows
    const int base = blockIdx.x * 32;
    unsigned long long acc2[8] = {0ull,0ull,0ull,0ull,0ull,0ull,0ull,0ull};
    #pragma unroll
    for (int k4 = 0; k4 < H1 / 4; k4++) {
        unsigned long long w0 = wsp[(2 * k4)     * H2 + cc];
        unsigned long long w1 = wsp[(2 * k4 + 1) * H2 + cc];
        #pragma unroll
        for (int r = 0; r < 8; r++) {
            ulonglong2 xv = *(const ulonglong2*)(ys + (ry * 8 + r) * H1 + k4 * 4);
            FMAX2(acc2[r], xv.x, w0);
            FMAX2(acc2[r], xv.y, w1);
        }
    }
    const float bb = b2[cc];
    int   curb = -1;
    float best = 0.f;
    #pragma unroll
    for (int r = 0; r < 8; r++) {
        int row = base + ry * 8 + r;
        if (row >= Nn) break;
        int   bt = batch[row];
        float lo, hi; unpk(acc2[r], lo, hi);
        float v = (lo + hi) + bb;
        if (bt != curb) {
            if (curb >= 0) atomicMax(&g_pool[(size_t)curb * H2 + cc], enc_f(best));
            curb = bt; best = v;
        } else if (v > best) best = v;
    }
    if (curb >= 0) atomicMax(&g_pool[(size_t)curb * H2 + cc], enc_f(best));
}

// ---------------- MLP head ---------------------------------------------------
__global__ void k_mlp(const float* __restrict__ l1W, const float* __restrict__ l1b,
                      const float* __restrict__ l2W, const float* __restrict__ l2b,
                      const float* __restrict__ l3W, const float* __restrict__ l3b,
                      float* __restrict__ out) {
    __shared__ float gv[H2], z1[128], z2[64];
    const int g = blockIdx.x, t = threadIdx.x;
    if (t < H2) gv[t] = dec_f(g_pool[g * H2 + t]);
    __syncthreads();
    {
        float acc = l1b[t];
        #pragma unroll 8
        for (int k = 0; k < 64; k++) acc += gv[k] * l1W[k * 128 + t];
        z1[t] = leaky(acc);
    }
    __syncthreads();
    if (t < 64) {
        float acc = l2b[t];
        #pragma unroll 8
        for (int k = 0; k < 128; k++) acc += z1[k] * l2W[k * 64 + t];
        z2[t] = leaky(acc);
    }
    __syncthreads();
    if (t < 64) {
        float acc = l3b[t];
        #pragma unroll 8
        for (int k = 0; k < 64; k++) acc += z2[k] * l3W[k * 64 + t];
        out[g * 64 + t] = acc;
    }
}

// ---------------- launch ------------------------------------------------------
extern "C" void kernel_launch(void* const* d_in, const int* in_sizes, int n_in,
                              void* d_out, int out_size) {
    const float* x    = (const float*)d_in[0];
    const int*   ei   = (const int*)  d_in[1];
    const int*   batch= (const int*)  d_in[2];
    const float* W1   = (const float*)d_in[3];
    const float* b1   = (const float*)d_in[4];
    const float* W2   = (const float*)d_in[5];
    const float* b2   = (const float*)d_in[6];
    const float* l1W  = (const float*)d_in[7];
    const float* l1b  = (const float*)d_in[8];
    const float* l2W  = (const float*)d_in[9];
    const float* l2b  = (const float*)d_in[10];
    const float* l3W  = (const float*)d_in[11];
    const float* l3b  = (const float*)d_in[12];
    float* out = (float*)d_out;

    const int E  = in_sizes[1] / 2;
    const int E4 = E / 4;
    const int* src = ei;
    const int* dst = ei + E;

    // side stream + fork/join events (created once, on the uncaptured
    // correctness call; capture-legal fork-join pattern thereafter)
    static cudaStream_t s2 = nullptr;
    static cudaEvent_t  evF = nullptr, evJ = nullptr;
    if (s2 == nullptr) {
        cudaStreamCreateWithFlags(&s2, cudaStreamNonBlocking);
        cudaEventCreateWithFlags(&evF, cudaEventDisableTiming);
        cudaEventCreateWithFlags(&evJ, cudaEventDisableTiming);
    }

    // fork: gemm1 (independent of CSR) on s2
    cudaEventRecord(evF, 0);
    cudaStreamWaitEvent(s2, evF, 0);
    k_gemm1<<<(Nn + 63) / 64, 256, 0, s2>>>(x, W1);
    cudaEventRecord(evJ, s2);

    // CSR build on the main (captured) stream
    k_init <<<(Nn + 255) / 256, 256>>>();
    k_cnt  <<<(E4 + 255) / 256, 256>>>(dst, E4);
    k_scanA<<<NSB, SB>>>();
    k_scanC<<<NSB, SB>>>();
    k_fill <<<(E4 + 255) / 256, 256>>>(src, dst, E4);

    // join, then the dependent chain
    cudaStreamWaitEvent(0, evJ, 0);
    k_scale<<<((Nn + 1) * (H1 / 4) + 255) / 256, 256>>>();
    k_gather1<<<(Nn * 8 + 255) / 256, 256>>>(b1);
    k_gather_gemm3<<<(Nn + 31) / 32, 256>>>(W2, b2, batch);
    k_mlp  <<<NG, 128>>>(l1W, l1b, l2W, l2b, l3W, l3b, out);
}

// round 14
// speedup vs baseline: 2.3941x; 1.0244x over previous
#include <cuda_runtime.h>

#define Nn   100000
#define Ee   3200000
#define FIN  128
#define H1   32
#define H2   64
#define NG   256

#define SB    256
#define NSB   ((Nn + SB - 1) / SB)       // 391
#define SRTSZ (Ee + 8 * Nn)              // padded CSR capacity

// ---------------- scratch (BSS zero-initialized; re-zeroed at tail) ---------
__device__ int      g_cnt[Nn];            // zero at launch start (invariant)
__device__ int      g_row[Nn + 1];
__device__ int      g_cur[Nn];
__device__ int      g_srt[SRTSZ];         // srcs sorted by dst, padded w/ Nn
__device__ int      g_part[NSB];
__device__ float    g_dinv[Nn];
__device__ float    g_h1 [(Nn + 1) * H1]; // raw x@W1, then *dinv ; row Nn = 0
__device__ float    g_x2 [(Nn + 1) * H1]; // leaky(a1+b1)*dinv ; row Nn = 0
__device__ unsigned g_pool[NG * H2];      // zero at launch start (invariant)

// ---------------- helpers ---------------------------------------------------
__device__ __forceinline__ float leaky(float v) { return v > 0.f ? v : 0.1f * v; }
__device__ __forceinline__ unsigned enc_f(float f) {
    unsigned u = __float_as_uint(f);
    return (u & 0x80000000u) ? ~u : (u | 0x80000000u);
}
__device__ __forceinline__ float dec_f(unsigned u) {
    return __uint_as_float((u & 0x80000000u) ? (u & 0x7fffffffu) : ~u);
}
#define ADDX2(acc, v) asm("add.rn.f32x2 %0, %0, %1;" : "+l"(acc) : "l"(v))
#define FMAX2(acc, a, b) asm("fma.rn.f32x2 %0, %1, %2, %0;" : "+l"(acc) : "l"(a), "l"(b))
__device__ __forceinline__ void unpk(unsigned long long a, float& lo, float& hi) {
    asm("mov.b64 {%0,%1}, %2;" : "=f"(lo), "=f"(hi) : "l"(a));
}
__device__ __forceinline__ unsigned long long pk(float lo, float hi) {
    unsigned long long r;
    asm("mov.b64 %0, {%1,%2};" : "=l"(r) : "f"(lo), "f"(hi));
    return r;
}

// ---------------- CSR build (main stream) ------------------------------------
__global__ void __launch_bounds__(256) k_cnt(const int* __restrict__ dst, int E4) {
    int t = blockIdx.x * blockDim.x + threadIdx.x;
    if (t < E4) {
        int4 d = *(const int4*)(dst + t * 4);
        atomicAdd(&g_cnt[d.x], 1);
        atomicAdd(&g_cnt[d.y], 1);
        atomicAdd(&g_cnt[d.z], 1);
        atomicAdd(&g_cnt[d.w], 1);
    }
}

__global__ void __launch_bounds__(SB) k_scanA() {     // padded per-block sums
    __shared__ int s[SB];
    int i = blockIdx.x * SB + threadIdx.x;
    int c = (i < Nn) ? g_cnt[i] : 0;
    s[threadIdx.x] = (c + 7) & ~7;
    __syncthreads();
    for (int d = SB / 2; d > 0; d >>= 1) {
        if (threadIdx.x < d) s[threadIdx.x] += s[threadIdx.x + d];
        __syncthreads();
    }
    if (threadIdx.x == 0) g_part[blockIdx.x] = s[0];
}

__global__ void __launch_bounds__(SB) k_scanC() {     // offsets + dinv + pads
    __shared__ int s[SB];
    __shared__ int off_sh;
    const int t = threadIdx.x, b = blockIdx.x;
    int p = 0;
    for (int i = t; i < b; i += SB) p += g_part[i];
    s[t] = p; __syncthreads();
    for (int d = SB / 2; d > 0; d >>= 1) {
        if (t < d) s[t] += s[t + d];
        __syncthreads();
    }
    if (t == 0) off_sh = s[0];
    __syncthreads();
    const int i = b * SB + t;
    const int c  = (i < Nn) ? g_cnt[i] : 0;
    const int pc = (c + 7) & ~7;
    s[t] = pc; __syncthreads();
    for (int d = 1; d < SB; d <<= 1) {   // inclusive scan
        int v = (t >= d) ? s[t - d] : 0;
        __syncthreads();
        s[t] += v;
        __syncthreads();
    }
    if (i < Nn) {
        int excl = off_sh + s[t] - pc;
        g_row[i]  = excl;
        g_cur[i]  = excl;
        g_dinv[i] = rsqrtf((float)(c + 1));
        for (int k = c; k < pc; k++) g_srt[excl + k] = Nn;   // dummy pads
    }
    if (b == NSB - 1 && t == SB - 1) g_row[Nn] = off_sh + s[SB - 1];
}

__global__ void __launch_bounds__(256) k_fill(const int* __restrict__ src,
                                              const int* __restrict__ dst, int E4) {
    int t = blockIdx.x * blockDim.x + threadIdx.x;
    if (t < E4) {
        int4 sv = *(const int4*)(src + t * 4);
        int4 dv = *(const int4*)(dst + t * 4);
        g_srt[atomicAdd(&g_cur[dv.x], 1)] = sv.x;
        g_srt[atomicAdd(&g_cur[dv.y], 1)] = sv.y;
        g_srt[atomicAdd(&g_cur[dv.z], 1)] = sv.z;
        g_srt[atomicAdd(&g_cur[dv.w], 1)] = sv.w;
    }
}

// ---------------- GEMM 1 (side stream): h1_raw = x @ W1 ----------------------
__global__ void __launch_bounds__(256) k_gemm1(const float* __restrict__ x,
                                               const float* __restrict__ W1) {
    __shared__ unsigned long long wsp[(FIN / 2) * H1];  // 16 KB
    __shared__ float xs[64 * FIN];                      // 32 KB
    const int tid = threadIdx.x;
    for (int i = tid; i < (FIN / 2) * H1; i += 256) {
        int k2 = i >> 5, c = i & 31;
        wsp[i] = pk(W1[(2 * k2) * H1 + c], W1[(2 * k2 + 1) * H1 + c]);
    }
    const int base = blockIdx.x * 64;
    for (int i = tid; i < 64 * (FIN / 4); i += 256) {
        int r = i >> 5, f = i & 31;
        int row = base + r;
        float4 v = make_float4(0.f, 0.f, 0.f, 0.f);
        if (row < Nn) v = *(const float4*)(x + (size_t)row * FIN + f * 4);
        *(float4*)(xs + r * FIN + f * 4) = v;
    }
    __syncthreads();
    const int cc = tid & 31, ry = tid >> 5;
    unsigned long long acc2[8] = {0ull,0ull,0ull,0ull,0ull,0ull,0ull,0ull};
    #pragma unroll 4
    for (int k4 = 0; k4 < FIN / 4; k4++) {
        unsigned long long w0 = wsp[(2 * k4)     * H1 + cc];
        unsigned long long w1 = wsp[(2 * k4 + 1) * H1 + cc];
        #pragma unroll
        for (int r = 0; r < 8; r++) {
            ulonglong2 xv = *(const ulonglong2*)(xs + (ry * 8 + r) * FIN + k4 * 4);
            FMAX2(acc2[r], xv.x, w0);
            FMAX2(acc2[r], xv.y, w1);
        }
    }
    #pragma unroll
    for (int r = 0; r < 8; r++) {
        int row = base + ry * 8 + r;
        if (row < Nn) {
            float lo, hi; unpk(acc2[r], lo, hi);
            g_h1[(size_t)row * H1 + cc] = lo + hi;      // RAW (dinv later)
        }
    }
}

// ---------------- scale (side stream, after scanC event): h1 *= dinv ---------
// also zeroes the dummy rows of h1 and x2 (state invariant for the gathers)
__global__ void __launch_bounds__(256) k_scale() {
    int t = blockIdx.x * 256 + threadIdx.x;             // one float4 each
    if (t >= (Nn + 1) * (H1 / 4)) return;
    int row = t >> 3;
    float4* p = (float4*)g_h1 + t;
    if (row < Nn) {
        float di = g_dinv[row];
        float4 v = *p;
        *p = make_float4(v.x * di, v.y * di, v.z * di, v.w * di);
    } else {
        *p = make_float4(0.f, 0.f, 0.f, 0.f);
        ((float4*)g_x2)[t] = make_float4(0.f, 0.f, 0.f, 0.f);
    }
}

// gather core: 8 lanes/node, 4 dims/lane, packed f32x2 accumulation.
// neighbor lists padded to multiples of 8 with dummy node Nn (zero row).
__device__ __forceinline__ void gather32(const float* __restrict__ in, int node, int c,
                                         unsigned long long& a01, unsigned long long& a23) {
    const ulonglong2* __restrict__ self =
        (const ulonglong2*)(in + (size_t)node * H1 + c * 4);
    ulonglong2 sv = *self;
    a01 = sv.x; a23 = sv.y;
    const int beg = __ldg(&g_row[node]), end = __ldg(&g_row[node + 1]);
    for (int e = beg; e < end; e += 8) {
        int4 ia = *(const int4*)(g_srt + e);
        int4 ib = *(const int4*)(g_srt + e + 4);
        ulonglong2 v;
        v = *(const ulonglong2*)(in + (size_t)ia.x * H1 + c * 4); ADDX2(a01, v.x); ADDX2(a23, v.y);
        v = *(const ulonglong2*)(in + (size_t)ia.y * H1 + c * 4); ADDX2(a01, v.x); ADDX2(a23, v.y);
        v = *(const ulonglong2*)(in + (size_t)ia.z * H1 + c * 4); ADDX2(a01, v.x); ADDX2(a23, v.y);
        v = *(const ulonglong2*)(in + (size_t)ia.w * H1 + c * 4); ADDX2(a01, v.x); ADDX2(a23, v.y);
        v = *(const ulonglong2*)(in + (size_t)ib.x * H1 + c * 4); ADDX2(a01, v.x); ADDX2(a23, v.y);
        v = *(const ulonglong2*)(in + (size_t)ib.y * H1 + c * 4); ADDX2(a01, v.x); ADDX2(a23, v.y);
        v = *(const ulonglong2*)(in + (size_t)ib.z * H1 + c * 4); ADDX2(a01, v.x); ADDX2(a23, v.y);
        v = *(const ulonglong2*)(in + (size_t)ib.w * H1 + c * 4); ADDX2(a01, v.x); ADDX2(a23, v.y);
    }
}

// ---------------- gather 1: x2 = leaky(agg*dinv + b1) * dinv -----------------
// tail duty: re-zero g_cnt for the next launch (it is dead after scanC)
__global__ void __launch_bounds__(256) k_gather1(const float* __restrict__ b1) {
    int tid = blockIdx.x * 256 + threadIdx.x;
    int node = tid >> 3, c = tid & 7;
    if (node >= Nn) return;
    unsigned long long a01, a23;
    gather32(g_h1, node, c, a01, a23);
    float di = g_dinv[node];
    float f0, f1, f2, f3;
    unpk(a01, f0, f1); unpk(a23, f2, f3);
    float4 bb = *(const float4*)(b1 + c * 4);
    float4 o;
    o.x = leaky(f0 * di + bb.x) * di;
    o.y = leaky(f1 * di + bb.y) * di;
    o.z = leaky(f2 * di + bb.z) * di;
    o.w = leaky(f3 * di + bb.w) * di;
    *(float4*)(g_x2 + (size_t)node * H1 + c * 4) = o;
    if (c == 0) g_cnt[node] = 0;            // restore invariant
}

// ---------------- gather 2 fused with GEMM3 (packed FMA) + max pool ----------
__global__ void __launch_bounds__(256) k_gather_gemm3(const float* __restrict__ W2,
                                                      const float* __restrict__ b2,
                                                      const int* __restrict__ batch) {
    __shared__ unsigned long long wsp[(H1 / 2) * H2];   // 8 KB
    __shared__ float ys[32 * H1];                       // 4 KB
    const int tid = threadIdx.x;
    for (int i = tid; i < (H1 / 2) * H2; i += 256) {
        int k2 = i >> 6, c = i & 63;
        wsp[i] = pk(W2[(2 * k2) * H2 + c], W2[(2 * k2 + 1) * H2 + c]);
    }
    const int nl = tid >> 3, c = tid & 7;
    const int node = blockIdx.x * 32 + nl;
    if (node < Nn) {
        unsigned long long a01, a23;
        gather32(g_x2, node, c, a01, a23);
        float di = g_dinv[node];
        float f0, f1, f2, f3;
        unpk(a01, f0, f1); unpk(a23, f2, f3);
        ys[nl * H1 + c * 4 + 0] = f0 * di;
        ys[nl * H1 + c * 4 + 1] = f1 * di;
        ys[nl * H1 + c * 4 + 2] = f2 * di;
        ys[nl * H1 + c * 4 + 3] = f3 * di;
    } else {
        ys[nl * H1 + c * 4 + 0] = 0.f; ys[nl * H1 + c * 4 + 1] = 0.f;
        ys[nl * H1 + c * 4 + 2] = 0.f; ys[nl * H1 + c * 4 + 3] = 0.f;
    }
    __syncthreads();
    const int cc = tid & 63, ry = tid >> 6;   // 4 groups x 8 rows
    const int base = blockIdx.x * 32;
    unsigned long long acc2[8] = {0ull,0ull,0ull,0ull,0ull,0ull,0ull,0ull};
    #pragma unroll
    for (int k4 = 0; k4 < H1 / 4; k4++) {
        unsigned long long w0 = wsp[(2 * k4)     * H2 + cc];
        unsigned long long w1 = wsp[(2 * k4 + 1) * H2 + cc];
        #pragma unroll
        for (int r = 0; r < 8; r++) {
            ulonglong2 xv = *(const ulonglong2*)(ys + (ry * 8 + r) * H1 + k4 * 4);
            FMAX2(acc2[r], xv.x, w0);
            FMAX2(acc2[r], xv.y, w1);
        }
    }
    const float bb = b2[cc];
    int   curb = -1;
    float best = 0.f;
    #pragma unroll
    for (int r = 0; r < 8; r++) {
        int row = base + ry * 8 + r;
        if (row >= Nn) break;
        int   bt = batch[row];
        float lo, hi; unpk(acc2[r], lo, hi);
        float v = (lo + hi) + bb;
        if (bt != curb) {
            if (curb >= 0) atomicMax(&g_pool[(size_t)curb * H2 + cc], enc_f(best));
            curb = bt; best = v;
        } else if (v > best) best = v;
    }
    if (curb >= 0) atomicMax(&g_pool[(size_t)curb * H2 + cc], enc_f(best));
}

// ---------------- MLP head (tail duty: re-zero g_pool) -----------------------
__global__ void __launch_bounds__(128) k_mlp(
        const float* __restrict__ l1W, const float* __restrict__ l1b,
        const float* __restrict__ l2W, const float* __restrict__ l2b,
        const float* __restrict__ l3W, const float* __restrict__ l3b,
        float* __restrict__ out) {
    __shared__ float gv[H2], z1[128], z2[64];
    const int g = blockIdx.x, t = threadIdx.x;
    if (t < H2) {
        gv[t] = dec_f(g_pool[g * H2 + t]);
        g_pool[g * H2 + t] = 0u;            // restore invariant
    }
    __syncthreads();
    {
        float acc = l1b[t];
        #pragma unroll 8
        for (int k = 0; k < 64; k++) acc += gv[k] * l1W[k * 128 + t];
        z1[t] = leaky(acc);
    }
    __syncthreads();
    if (t < 64) {
        float acc = l2b[t];
        #pragma unroll 8
        for (int k = 0; k < 128; k++) acc += z1[k] * l2W[k * 64 + t];
        z2[t] = leaky(acc);
    }
    __syncthreads();
    if (t < 64) {
        float acc = l3b[t];
        #pragma unroll 8
        for (int k = 0; k < 64; k++) acc += z2[k] * l3W[k * 64 + t];
        out[g * 64 + t] = acc;
    }
}

// ---------------- launch ------------------------------------------------------
extern "C" void kernel_launch(void* const* d_in, const int* in_sizes, int n_in,
                              void* d_out, int out_size) {
    const float* x    = (const float*)d_in[0];
    const int*   ei   = (const int*)  d_in[1];
    const int*   batch= (const int*)  d_in[2];
    const float* W1   = (const float*)d_in[3];
    const float* b1   = (const float*)d_in[4];
    const float* W2   = (const float*)d_in[5];
    const float* b2   = (const float*)d_in[6];
    const float* l1W  = (const float*)d_in[7];
    const float* l1b  = (const float*)d_in[8];
    const float* l2W  = (const float*)d_in[9];
    const float* l2b  = (const float*)d_in[10];
    const float* l3W  = (const float*)d_in[11];
    const float* l3b  = (const float*)d_in[12];
    float* out = (float*)d_out;

    const int E  = in_sizes[1] / 2;
    const int E4 = E / 4;
    const int* src = ei;
    const int* dst = ei + E;

    static cudaStream_t s2 = nullptr;
    static cudaEvent_t  evF = nullptr, evC = nullptr, evJ = nullptr;
    if (s2 == nullptr) {
        cudaStreamCreateWithFlags(&s2, cudaStreamNonBlocking);
        cudaEventCreateWithFlags(&evF, cudaEventDisableTiming);
        cudaEventCreateWithFlags(&evC, cudaEventDisableTiming);
        cudaEventCreateWithFlags(&evJ, cudaEventDisableTiming);
    }

    // fork: gemm1 on s2 (independent of CSR)
    cudaEventRecord(evF, 0);
    cudaStreamWaitEvent(s2, evF, 0);
    k_gemm1<<<(Nn + 63) / 64, 256, 0, s2>>>(x, W1);

    // CSR build on main stream
    k_cnt  <<<(E4 + 255) / 256, 256>>>(dst, E4);
    k_scanA<<<NSB, SB>>>();
    k_scanC<<<NSB, SB>>>();
    cudaEventRecord(evC, 0);                      // dinv ready
    k_fill <<<(E4 + 255) / 256, 256>>>(src, dst, E4);

    // scale on s2 (needs gemm1 + dinv), overlaps k_fill
    cudaStreamWaitEvent(s2, evC, 0);
    k_scale<<<((Nn + 1) * (H1 / 4) + 255) / 256, 256, 0, s2>>>();
    cudaEventRecord(evJ, s2);

    // join, then the dependent chain
    cudaStreamWaitEvent(0, evJ, 0);
    k_gather1<<<(Nn * 8 + 255) / 256, 256>>>(b1);
    k_gather_gemm3<<<(Nn + 31) / 32, 256>>>(W2, b2, batch);
    k_mlp  <<<NG, 128>>>(l1W, l1b, l2W, l2b, l3W, l3b, out);
}

// round 17
// speedup vs baseline: 2.6575x; 1.1100x over previous
#include <cuda_runtime.h>
#include <cuda_fp16.h>

#define Nn   100000
#define Ee   3200000
#define FIN  128
#define H1   32
#define H2   64
#define NG   256

#define SB    256
#define NSB   ((Nn + SB - 1) / SB)       // 391
#define SRTSZ (Ee + 8 * Nn)              // padded CSR capacity

// ---------------- scratch (BSS zero-initialized; re-zeroed at tail) ---------
__device__ int      g_cnt[Nn];            // zero at launch start (invariant)
__device__ int      g_row[Nn + 1];
__device__ int      g_cur[Nn];
__device__ int      g_srt[SRTSZ];         // srcs sorted by dst, padded w/ Nn
__device__ int      g_part[NSB];
__device__ float    g_dinv[Nn];
__device__ float    g_h1f[Nn * H1];       // raw x@W1 (fp32, pre-scale)
__device__ __half   g_h1h[(Nn + 1) * H1]; // (x@W1)*dinv fp16 ; row Nn = 0
__device__ __half   g_x2h[(Nn + 1) * H1]; // leaky(a1+b1)*dinv fp16 ; row Nn = 0
__device__ unsigned g_pool[NG * H2];      // zero at launch start (invariant)

// ---------------- helpers ---------------------------------------------------
__device__ __forceinline__ float leaky(float v) { return v > 0.f ? v : 0.1f * v; }
__device__ __forceinline__ unsigned enc_f(float f) {
    unsigned u = __float_as_uint(f);
    return (u & 0x80000000u) ? ~u : (u | 0x80000000u);
}
__device__ __forceinline__ float dec_f(unsigned u) {
    return __uint_as_float((u & 0x80000000u) ? (u & 0x7fffffffu) : ~u);
}
#define FMAX2(acc, a, b) asm("fma.rn.f32x2 %0, %1, %2, %0;" : "+l"(acc) : "l"(a), "l"(b))
__device__ __forceinline__ void unpk(unsigned long long a, float& lo, float& hi) {
    asm("mov.b64 {%0,%1}, %2;" : "=f"(lo), "=f"(hi) : "l"(a));
}
__device__ __forceinline__ unsigned long long pk(float lo, float hi) {
    unsigned long long r;
    asm("mov.b64 %0, {%1,%2};" : "=l"(r) : "f"(lo), "f"(hi));
    return r;
}
__device__ __forceinline__ unsigned h2bits(__half2 h) {
    return *reinterpret_cast<unsigned*>(&h);
}

// ---------------- CSR build (main stream) ------------------------------------
__global__ void __launch_bounds__(256) k_cnt(const int* __restrict__ dst, int E4) {
    int t = blockIdx.x * blockDim.x + threadIdx.x;
    if (t < E4) {
        int4 d = *(const int4*)(dst + t * 4);
        atomicAdd(&g_cnt[d.x], 1);
        atomicAdd(&g_cnt[d.y], 1);
        atomicAdd(&g_cnt[d.z], 1);
        atomicAdd(&g_cnt[d.w], 1);
    }
}

__global__ void __launch_bounds__(SB) k_scanA() {     // padded per-block sums
    __shared__ int s[SB];
    int i = blockIdx.x * SB + threadIdx.x;
    int c = (i < Nn) ? g_cnt[i] : 0;
    s[threadIdx.x] = (c + 7) & ~7;
    __syncthreads();
    for (int d = SB / 2; d > 0; d >>= 1) {
        if (threadIdx.x < d) s[threadIdx.x] += s[threadIdx.x + d];
        __syncthreads();
    }
    if (threadIdx.x == 0) g_part[blockIdx.x] = s[0];
}

__global__ void __launch_bounds__(SB) k_scanC() {     // offsets + dinv + pads
    __shared__ int s[SB];
    __shared__ int off_sh;
    const int t = threadIdx.x, b = blockIdx.x;
    int p = 0;
    for (int i = t; i < b; i += SB) p += g_part[i];
    s[t] = p; __syncthreads();
    for (int d = SB / 2; d > 0; d >>= 1) {
        if (t < d) s[t] += s[t + d];
        __syncthreads();
    }
    if (t == 0) off_sh = s[0];
    __syncthreads();
    const int i = b * SB + t;
    const int c  = (i < Nn) ? g_cnt[i] : 0;
    const int pc = (c + 7) & ~7;
    s[t] = pc; __syncthreads();
    for (int d = 1; d < SB; d <<= 1) {   // inclusive scan
        int v = (t >= d) ? s[t - d] : 0;
        __syncthreads();
        s[t] += v;
        __syncthreads();
    }
    if (i < Nn) {
        int excl = off_sh + s[t] - pc;
        g_row[i]  = excl;
        g_cur[i]  = excl;
        g_dinv[i] = rsqrtf((float)(c + 1));
        for (int k = c; k < pc; k++) g_srt[excl + k] = Nn;   // dummy pads
    }
    if (b == NSB - 1 && t == SB - 1) g_row[Nn] = off_sh + s[SB - 1];
}

__global__ void __launch_bounds__(256) k_fill(const int* __restrict__ src,
                                              const int* __restrict__ dst, int E4) {
    int t = blockIdx.x * blockDim.x + threadIdx.x;
    if (t < E4) {
        int4 sv = *(const int4*)(src + t * 4);
        int4 dv = *(const int4*)(dst + t * 4);
        g_srt[atomicAdd(&g_cur[dv.x], 1)] = sv.x;
        g_srt[atomicAdd(&g_cur[dv.y], 1)] = sv.y;
        g_srt[atomicAdd(&g_cur[dv.z], 1)] = sv.z;
        g_srt[atomicAdd(&g_cur[dv.w], 1)] = sv.w;
    }
}

// ---------------- GEMM 1 (side stream): h1f = x @ W1 (raw fp32) --------------
__global__ void __launch_bounds__(256) k_gemm1(const float* __restrict__ x,
                                               const float* __restrict__ W1) {
    __shared__ unsigned long long wsp[(FIN / 2) * H1];  // 16 KB
    __shared__ float xs[64 * FIN];                      // 32 KB
    const int tid = threadIdx.x;
    for (int i = tid; i < (FIN / 2) * H1; i += 256) {
        int k2 = i >> 5, c = i & 31;
        wsp[i] = pk(W1[(2 * k2) * H1 + c], W1[(2 * k2 + 1) * H1 + c]);
    }
    const int base = blockIdx.x * 64;
    for (int i = tid; i < 64 * (FIN / 4); i += 256) {
        int r = i >> 5, f = i & 31;
        int row = base + r;
        float4 v = make_float4(0.f, 0.f, 0.f, 0.f);
        if (row < Nn) v = *(const float4*)(x + (size_t)row * FIN + f * 4);
        *(float4*)(xs + r * FIN + f * 4) = v;
    }
    __syncthreads();
    const int cc = tid & 31, ry = tid >> 5;
    unsigned long long acc2[8] = {0ull,0ull,0ull,0ull,0ull,0ull,0ull,0ull};
    #pragma unroll 4
    for (int k4 = 0; k4 < FIN / 4; k4++) {
        unsigned long long w0 = wsp[(2 * k4)     * H1 + cc];
        unsigned long long w1 = wsp[(2 * k4 + 1) * H1 + cc];
        #pragma unroll
        for (int r = 0; r < 8; r++) {
            ulonglong2 xv = *(const ulonglong2*)(xs + (ry * 8 + r) * FIN + k4 * 4);
            FMAX2(acc2[r], xv.x, w0);
            FMAX2(acc2[r], xv.y, w1);
        }
    }
    #pragma unroll
    for (int r = 0; r < 8; r++) {
        int row = base + ry * 8 + r;
        if (row < Nn) {
            float lo, hi; unpk(acc2[r], lo, hi);
            g_h1f[(size_t)row * H1 + cc] = lo + hi;
        }
    }
}

// ---------------- scale (side stream): h1h = fp16(h1f * dinv) ----------------
// single rounding per feature; also zeroes dummy rows of h1h and x2h
__global__ void __launch_bounds__(256) k_scale() {
    int t = blockIdx.x * 256 + threadIdx.x;             // one float4 / uint2 each
    if (t >= (Nn + 1) * (H1 / 4)) return;
    int row = t >> 3;
    if (row < Nn) {
        float di = g_dinv[row];
        float4 v = ((const float4*)g_h1f)[t];
        __half2 a = __floats2half2_rn(v.x * di, v.y * di);
        __half2 b = __floats2half2_rn(v.z * di, v.w * di);
        ((uint2*)g_h1h)[t] = make_uint2(h2bits(a), h2bits(b));
    } else {
        ((uint2*)g_h1h)[t] = make_uint2(0u, 0u);
        ((uint2*)g_x2h)[t] = make_uint2(0u, 0u);
    }
}

// gather core (fp16 rows): 8 lanes/node, 4 halfs/lane (8B), fp32 accumulation.
// neighbor lists padded to multiples of 8 with dummy node Nn (zero row).
__device__ __forceinline__ void gadd(const __half* __restrict__ in, size_t off,
                                     float& a0, float& a1, float& a2, float& a3) {
    uint2 v = *(const uint2*)(in + off);
    float2 f01 = __half22float2(*reinterpret_cast<__half2*>(&v.x));
    float2 f23 = __half22float2(*reinterpret_cast<__half2*>(&v.y));
    a0 += f01.x; a1 += f01.y; a2 += f23.x; a3 += f23.y;
}

__device__ __forceinline__ void gather16(const __half* __restrict__ in, int node, int c,
                                         float& a0, float& a1, float& a2, float& a3) {
    const size_t lane_off = (size_t)c * 4;
    a0 = a1 = a2 = a3 = 0.f;
    gadd(in, (size_t)node * H1 + lane_off, a0, a1, a2, a3);   // self
    const int beg = __ldg(&g_row[node]), end = __ldg(&g_row[node + 1]);
    for (int e = beg; e < end; e += 8) {
        int4 ia = *(const int4*)(g_srt + e);
        int4 ib = *(const int4*)(g_srt + e + 4);
        gadd(in, (size_t)ia.x * H1 + lane_off, a0, a1, a2, a3);
        gadd(in, (size_t)ia.y * H1 + lane_off, a0, a1, a2, a3);
        gadd(in, (size_t)ia.z * H1 + lane_off, a0, a1, a2, a3);
        gadd(in, (size_t)ia.w * H1 + lane_off, a0, a1, a2, a3);
        gadd(in, (size_t)ib.x * H1 + lane_off, a0, a1, a2, a3);
        gadd(in, (size_t)ib.y * H1 + lane_off, a0, a1, a2, a3);
        gadd(in, (size_t)ib.z * H1 + lane_off, a0, a1, a2, a3);
        gadd(in, (size_t)ib.w * H1 + lane_off, a0, a1, a2, a3);
    }
}

// ---------------- gather 1: x2h = fp16(leaky(agg*dinv + b1) * dinv) ----------
// tail duty: re-zero g_cnt for the next launch (dead after scanC)
__global__ void __launch_bounds__(256) k_gather1(const float* __restrict__ b1) {
    int tid = blockIdx.x * 256 + threadIdx.x;
    int node = tid >> 3, c = tid & 7;
    if (node >= Nn) return;
    float f0, f1, f2, f3;
    gather16(g_h1h, node, c, f0, f1, f2, f3);
    float di = g_dinv[node];
    float4 bb = *(const float4*)(b1 + c * 4);
    float o0 = leaky(f0 * di + bb.x) * di;
    float o1 = leaky(f1 * di + bb.y) * di;
    float o2 = leaky(f2 * di + bb.z) * di;
    float o3 = leaky(f3 * di + bb.w) * di;
    __half2 pa = __floats2half2_rn(o0, o1);
    __half2 pb = __floats2half2_rn(o2, o3);
    *(uint2*)(g_x2h + (size_t)node * H1 + c * 4) = make_uint2(h2bits(pa), h2bits(pb));
    if (c == 0) g_cnt[node] = 0;            // restore invariant
}

// ---------------- gather 2 fused with GEMM3 (packed FMA) + max pool ----------
__global__ void __launch_bounds__(256) k_gather_gemm3(const float* __restrict__ W2,
                                                      const float* __restrict__ b2,
                                                      const int* __restrict__ batch) {
    __shared__ unsigned long long wsp[(H1 / 2) * H2];   // 8 KB
    __shared__ float ys[32 * H1];                       // 4 KB
    const int tid = threadIdx.x;
    for (int i = tid; i < (H1 / 2) * H2; i += 256) {
        int k2 = i >> 6, c = i & 63;
        wsp[i] = pk(W2[(2 * k2) * H2 + c], W2[(2 * k2 + 1) * H2 + c]);
    }
    const int nl = tid >> 3, c = tid & 7;
    const int node = blockIdx.x * 32 + nl;
    if (node < Nn) {
        float f0, f1, f2, f3;
        gather16(g_x2h, node, c, f0, f1, f2, f3);
        float di = g_dinv[node];
        ys[nl * H1 + c * 4 + 0] = f0 * di;
        ys[nl * H1 + c * 4 + 1] = f1 * di;
        ys[nl * H1 + c * 4 + 2] = f2 * di;
        ys[nl * H1 + c * 4 + 3] = f3 * di;
    } else {
        ys[nl * H1 + c * 4 + 0] = 0.f; ys[nl * H1 + c * 4 + 1] = 0.f;
        ys[nl * H1 + c * 4 + 2] = 0.f; ys[nl * H1 + c * 4 + 3] = 0.f;
    }
    __syncthreads();
    const int cc = tid & 63, ry = tid >> 6;   // 4 groups x 8 rows
    const int base = blockIdx.x * 32;
    unsigned long long acc2[8] = {0ull,0ull,0ull,0ull,0ull,0ull,0ull,0ull};
    #pragma unroll
    for (int k4 = 0; k4 < H1 / 4; k4++) {
        unsigned long long w0 = wsp[(2 * k4)     * H2 + cc];
        unsigned long long w1 = wsp[(2 * k4 + 1) * H2 + cc];
        #pragma unroll
        for (int r = 0; r < 8; r++) {
            ulonglong2 xv = *(const ulonglong2*)(ys + (ry * 8 + r) * H1 + k4 * 4);
            FMAX2(acc2[r], xv.x, w0);
            FMAX2(acc2[r], xv.y, w1);
        }
    }
    const float bb = b2[cc];
    int   curb = -1;
    float best = 0.f;
    #pragma unroll
    for (int r = 0; r < 8; r++) {
        int row = base + ry * 8 + r;
        if (row >= Nn) break;
        int   bt = batch[row];
        float lo, hi; unpk(acc2[r], lo, hi);
        float v = (lo + hi) + bb;
        if (bt != curb) {
            if (curb >= 0) atomicMax(&g_pool[(size_t)curb * H2 + cc], enc_f(best));
            curb = bt; best = v;
        } else if (v > best) best = v;
    }
    if (curb >= 0) atomicMax(&g_pool[(size_t)curb * H2 + cc], enc_f(best));
}

// ---------------- MLP head (tail duty: re-zero g_pool) -----------------------
__global__ void __launch_bounds__(128) k_mlp(
        const float* __restrict__ l1W, const float* __restrict__ l1b,
        const float* __restrict__ l2W, const float* __restrict__ l2b,
        const float* __restrict__ l3W, const float* __restrict__ l3b,
        float* __restrict__ out) {
    __shared__ float gv[H2], z1[128], z2[64];
    const int g = blockIdx.x, t = threadIdx.x;
    if (t < H2) {
        gv[t] = dec_f(g_pool[g * H2 + t]);
        g_pool[g * H2 + t] = 0u;            // restore invariant
    }
    __syncthreads();
    {
        float acc = l1b[t];
        #pragma unroll 8
        for (int k = 0; k < 64; k++) acc += gv[k] * l1W[k * 128 + t];
        z1[t] = leaky(acc);
    }
    __syncthreads();
    if (t < 64) {
        float acc = l2b[t];
        #pragma unroll 8
        for (int k = 0; k < 128; k++) acc += z1[k] * l2W[k * 64 + t];
        z2[t] = leaky(acc);
    }
    __syncthreads();
    if (t < 64) {
        float acc = l3b[t];
        #pragma unroll 8
        for (int k = 0; k < 64; k++) acc += z2[k] * l3W[k * 64 + t];
        out[g * 64 + t] = acc;
    }
}

// ---------------- launch ------------------------------------------------------
extern "C" void kernel_launch(void* const* d_in, const int* in_sizes, int n_in,
                              void* d_out, int out_size) {
    const float* x    = (const float*)d_in[0];
    const int*   ei   = (const int*)  d_in[1];
    const int*   batch= (const int*)  d_in[2];
    const float* W1   = (const float*)d_in[3];
    const float* b1   = (const float*)d_in[4];
    const float* W2   = (const float*)d_in[5];
    const float* b2   = (const float*)d_in[6];
    const float* l1W  = (const float*)d_in[7];
    const float* l1b  = (const float*)d_in[8];
    const float* l2W  = (const float*)d_in[9];
    const float* l2b  = (const float*)d_in[10];
    const float* l3W  = (const float*)d_in[11];
    const float* l3b  = (const float*)d_in[12];
    float* out = (float*)d_out;

    const int E  = in_sizes[1] / 2;
    const int E4 = E / 4;
    const int* src = ei;
    const int* dst = ei + E;

    static cudaStream_t s2 = nullptr;
    static cudaEvent_t  evF = nullptr, evC = nullptr, evJ = nullptr;
    if (s2 == nullptr) {
        cudaStreamCreateWithFlags(&s2, cudaStreamNonBlocking);
        cudaEventCreateWithFlags(&evF, cudaEventDisableTiming);
        cudaEventCreateWithFlags(&evC, cudaEventDisableTiming);
        cudaEventCreateWithFlags(&evJ, cudaEventDisableTiming);
    }

    // fork: gemm1 on s2 (independent of CSR)
    cudaEventRecord(evF, 0);
    cudaStreamWaitEvent(s2, evF, 0);
    k_gemm1<<<(Nn + 63) / 64, 256, 0, s2>>>(x, W1);

    // CSR build on main stream
    k_cnt  <<<(E4 + 255) / 256, 256>>>(dst, E4);
    k_scanA<<<NSB, SB>>>();
    k_scanC<<<NSB, SB>>>();
    cudaEventRecord(evC, 0);                      // dinv ready
    k_fill <<<(E4 + 255) / 256, 256>>>(src, dst, E4);

    // scale on s2 (needs gemm1 + dinv), overlaps k_fill
    cudaStreamWaitEvent(s2, evC, 0);
    k_scale<<<((Nn + 1) * (H1 / 4) + 255) / 256, 256, 0, s2>>>();
    cudaEventRecord(evJ, s2);

    // join, then the dependent chain
    cudaStreamWaitEvent(0, evJ, 0);
    k_gather1<<<(Nn * 8 + 255) / 256, 256>>>(b1);
    k_gather_gemm3<<<(Nn + 31) / 32, 256>>>(W2, b2, batch);
    k_mlp  <<<NG, 128>>>(l1W, l1b, l2W, l2b, l3W, l3b, out);
}